// round 14
// baseline (speedup 1.0000x reference)
#include <cuda_runtime.h>
#include <cuda_bf16.h>
#include <math.h>
#include <stdint.h>

// Problem constants
#define BB      8
#define LL      1024
#define DD      640
#define HH      10
#define FFD     1280
#define NLAYERS 6
#define MTOK    (BB * LL)      // 8192 tokens per input
#define MT2     (2 * MTOK)     // both inputs batched: 16384 tokens
#define QT      32             // queries per attention block
#define KW      160            // key window per block

// ---------------------------------------------------------------------------
// Static device scratch (both sequences concatenated)
// ---------------------------------------------------------------------------
__device__ float g_h   [MT2 * DD];
__device__ float g_qkv [MT2 * 3 * DD];
__device__ float g_d   [MT2 * DD];
__device__ __nv_bfloat16 g_h_hi [MT2 * DD],  g_h_lo [MT2 * DD];
__device__ __nv_bfloat16 g_ao_hi[MT2 * DD],  g_ao_lo[MT2 * DD];
__device__ __nv_bfloat16 g_f1_hi[MT2 * FFD], g_f1_lo[MT2 * FFD];

#define WQKV_N (NLAYERS * 3 * DD * DD)
#define WO_N   (NLAYERS * DD * DD)
#define W1_N   (NLAYERS * FFD * DD)
#define W2_N   (NLAYERS * DD * FFD)
__device__ __nv_bfloat16 g_wqkv_hi[WQKV_N], g_wqkv_lo[WQKV_N];
__device__ __nv_bfloat16 g_wo_hi  [WO_N],   g_wo_lo  [WO_N];
__device__ __nv_bfloat16 g_w1_hi  [W1_N],   g_w1_lo  [W1_N];
__device__ __nv_bfloat16 g_w2_hi  [W2_N],   g_w2_lo  [W2_N];

__device__ float g_pp  [2 * BB * 16 * DD];
__device__ float g_pool[2 * BB * DD];
__device__ float g_e   [2 * BB * DD];

// ---------------------------------------------------------------------------
// PTX helpers (non-'a' instructions only: mma.sync / ldmatrix / cp.async)
// ---------------------------------------------------------------------------
__device__ __forceinline__ uint32_t s2u(const void* p) {
    uint32_t a;
    asm("{ .reg .u64 t; cvta.to.shared.u64 t, %1; cvt.u32.u64 %0, t; }"
        : "=r"(a) : "l"(p));
    return a;
}

__device__ __forceinline__ void ldsm4(uint32_t* r, uint32_t addr) {
    asm volatile("ldmatrix.sync.aligned.m8n8.x4.shared.b16 {%0,%1,%2,%3}, [%4];"
                 : "=r"(r[0]), "=r"(r[1]), "=r"(r[2]), "=r"(r[3]) : "r"(addr));
}

__device__ __forceinline__ void mma16816(float* c, const uint32_t* a,
                                         const uint32_t* b) {
    asm volatile(
        "mma.sync.aligned.m16n8k16.row.col.f32.bf16.bf16.f32 "
        "{%0,%1,%2,%3}, {%4,%5,%6,%7}, {%8,%9}, {%0,%1,%2,%3};"
        : "+f"(c[0]), "+f"(c[1]), "+f"(c[2]), "+f"(c[3])
        : "r"(a[0]), "r"(a[1]), "r"(a[2]), "r"(a[3]), "r"(b[0]), "r"(b[1]));
}

#define CPA16(dst, src) \
    asm volatile("cp.async.cg.shared.global [%0], [%1], 16;" \
                 :: "r"(dst), "l"(src))
#define CPCOMMIT() asm volatile("cp.async.commit_group;" ::: "memory")
#define CPWAIT0()  asm volatile("cp.async.wait_group 0;" ::: "memory")
#define STSZERO(dst) \
    asm volatile("st.shared.v4.b32 [%0], {%1,%1,%1,%1};" \
                 :: "r"(dst), "r"(0u) : "memory")

// ---------------------------------------------------------------------------
// mma.sync split-precision GEMM, 3-CTA/SM config:
//   C[M,N] = (Ahi+Alo)[M,K] @ (Bhi+Blo)[N,K]^T + bias   (lo*lo dropped)
// CTA tile 128x64, 256 threads (8 warps, 4x2; warp tile 32x32).
// Stage = 32-wide K slice, TWO 64B K-rows packed per 128B smem line:
//   chunk(row, kc) = ((row&1)<<2 | kc) ^ ((row>>1)&7)
// (ldmatrix's 16 lanes hit each bank exactly twice = 2 phases = optimal).
// Stage = Ahi|Alo (8KB) + Bhi|Blo (4KB) = 24KB; double-buffered = 48KB ->
// THREE CTAs PER SM (24 warps, 37.5% occ): staggered stage barriers keep the
// tensor port fed through each CTA's drain (ncu R13: tensor=62.7% @ 2 CTAs).
// fp32 register accumulation.
// ---------------------------------------------------------------------------
#define OPTA  8192                   // A tile: 128 rows x 64B (64 lines)
#define OPTB  4096                   // B tile:  64 rows x 64B (32 lines)
#define SSTG  (2 * OPTA + 2 * OPTB)  // 24KB
#define NSTG  2
#define GSMEM (NSTG * SSTG)          // 48KB

__global__ __launch_bounds__(256, 3) void gemm_mma(
    const __nv_bfloat16* __restrict__ Ahi, const __nv_bfloat16* __restrict__ Alo,
    const __nv_bfloat16* __restrict__ Bhi, const __nv_bfloat16* __restrict__ Blo,
    const float* __restrict__ bias, float* __restrict__ C,
    __nv_bfloat16* __restrict__ Chi, __nv_bfloat16* __restrict__ Clo,
    int M, int N, int K, int relu)
{
    extern __shared__ char smraw[];
    const uint32_t sb = s2u(smraw);

    const int tid  = threadIdx.x;
    const int wid  = tid >> 5;
    const int lane = tid & 31;
    const int bm   = blockIdx.y * 128;
    const int bn   = blockIdx.x * 64;
    const int wm   = wid >> 1;       // 0..3 (32 rows)
    const int wn   = wid & 1;        // 0..1 (32 cols)

    float acc[2][4][4];
    #pragma unroll
    for (int i = 0; i < 2; i++)
        #pragma unroll
        for (int j = 0; j < 4; j++)
            #pragma unroll
            for (int r = 0; r < 4; r++) acc[i][j][r] = 0.f;

    const int nst = K >> 5;          // 32-wide K slices

    // loader: 6 cp.async per thread per stage.
    // A ops: rows lrA, lrA+64 (x2 operands); B ops: row lrA (x2 operands).
    const int lrA = tid >> 2;               // 0..63
    const int lkc = tid & 3;                // 16B chunk within 64B row
    const uint32_t dst0 =
        (uint32_t)((lrA >> 1) << 7) +
        (uint32_t)(((((lrA & 1) << 2) | lkc) ^ ((lrA >> 1) & 7)) << 4);
    // row +64: line +32 (==0 mod 8, same swizzle) -> dst + 4096

    #define LOADSTAGE(S) do {                                               \
        int col = ((S) << 5) + (lkc << 3);                                  \
        uint32_t base = sb + ((S) & 1) * SSTG;                              \
        CPA16(base + dst0,                                                  \
              Ahi + (size_t)(bm + lrA) * K + col);                          \
        CPA16(base + 4096 + dst0,                                           \
              Ahi + (size_t)(bm + lrA + 64) * K + col);                     \
        CPA16(base + OPTA + dst0,                                           \
              Alo + (size_t)(bm + lrA) * K + col);                          \
        CPA16(base + OPTA + 4096 + dst0,                                    \
              Alo + (size_t)(bm + lrA + 64) * K + col);                     \
        CPA16(base + 2 * OPTA + dst0,                                       \
              Bhi + (size_t)(bn + lrA) * K + col);                          \
        CPA16(base + 2 * OPTA + OPTB + dst0,                                \
              Blo + (size_t)(bn + lrA) * K + col);                          \
    } while (0)

    // fragment addressing: tile row gr = base16 + lr (base16 multiple of 16)
    // line = gr>>1, chunk = ((gr&1)<<2 | ch) ^ (line&7), ch = kk*2+lh
    const int lr      = lane & 15;
    const int lh      = lane >> 4;
    const int laneLn  = lr >> 1;            // 0..7 == (gr>>1)&7
    const int laneOdd = (lr & 1) << 2;
    const uint32_t arow0 = (uint32_t)((wm * 16 + 0 + laneLn) << 7);
    const uint32_t arow1 = (uint32_t)((wm * 16 + 8 + laneLn) << 7);
    const uint32_t brow0 = (uint32_t)((wn * 16 + 0 + laneLn) << 7);
    const uint32_t brow1 = (uint32_t)((wn * 16 + 8 + laneLn) << 7);

    LOADSTAGE(0); CPCOMMIT();
    CPWAIT0();
    __syncthreads();           // stage 0 visible to all warps

    for (int s = 0; s < nst; s++) {
        // Prefetch s+1 into the buffer consumed in stage s-1 (fully read
        // before the barrier that ended stage s-1).
        if (s + 1 < nst) LOADSTAGE(s + 1);
        CPCOMMIT();            // uniform group accounting

        const uint32_t sS   = sb + (s & 1) * SSTG;
        const uint32_t sAhi = sS;
        const uint32_t sAlo = sS + OPTA;
        const uint32_t sBhi = sS + 2 * OPTA;
        const uint32_t sBlo = sS + 2 * OPTA + OPTB;

        #pragma unroll
        for (int kk = 0; kk < 2; kk++) {
            const uint32_t chs = (uint32_t)(
                ((laneOdd | ((kk << 1) | lh)) ^ laneLn) << 4);
            uint32_t ah[2][4], al[2][4];
            uint32_t bh[2][2], bl[2][2], bh2[2][2], bl2[2][2];
            uint32_t r[4];

            // all 8 ldsm up front, then 24 MMAs back-to-back
            ldsm4(ah[0], sAhi + arow0 + chs);
            ldsm4(ah[1], sAhi + arow1 + chs);
            ldsm4(al[0], sAlo + arow0 + chs);
            ldsm4(al[1], sAlo + arow1 + chs);
            ldsm4(r, sBhi + brow0 + chs);
            bh[0][0] = r[0]; bh[0][1] = r[2];
            bh[1][0] = r[1]; bh[1][1] = r[3];
            ldsm4(r, sBlo + brow0 + chs);
            bl[0][0] = r[0]; bl[0][1] = r[2];
            bl[1][0] = r[1]; bl[1][1] = r[3];
            ldsm4(r, sBhi + brow1 + chs);
            bh2[0][0] = r[0]; bh2[0][1] = r[2];
            bh2[1][0] = r[1]; bh2[1][1] = r[3];
            ldsm4(r, sBlo + brow1 + chs);
            bl2[0][0] = r[0]; bl2[0][1] = r[2];
            bl2[1][0] = r[1]; bl2[1][1] = r[3];

            #pragma unroll
            for (int mt = 0; mt < 2; mt++) {
                #pragma unroll
                for (int nt = 0; nt < 2; nt++) {
                    mma16816(acc[mt][nt],     ah[mt], bh[nt]);
                    mma16816(acc[mt][nt],     ah[mt], bl[nt]);
                    mma16816(acc[mt][nt],     al[mt], bh[nt]);
                    mma16816(acc[mt][nt + 2], ah[mt], bh2[nt]);
                    mma16816(acc[mt][nt + 2], ah[mt], bl2[nt]);
                    mma16816(acc[mt][nt + 2], al[mt], bh2[nt]);
                }
            }
        }

        CPWAIT0();             // stage s+1 loads complete
        __syncthreads();       // stage s+1 visible; all warps done with s
    }

    // Epilogue
    const int group = lane >> 2;
    const int tig   = lane & 3;
    #pragma unroll
    for (int mt = 0; mt < 2; mt++) {
        #pragma unroll
        for (int half = 0; half < 2; half++) {
            const int row = bm + wm * 32 + mt * 16 + group + half * 8;
            #pragma unroll
            for (int nt = 0; nt < 4; nt++) {
                const int col = bn + wn * 32 + nt * 8 + tig * 2;
                float v0 = acc[mt][nt][half * 2 + 0] + bias[col];
                float v1 = acc[mt][nt][half * 2 + 1] + bias[col + 1];
                if (relu) { v0 = fmaxf(v0, 0.f); v1 = fmaxf(v1, 0.f); }
                if (C) {
                    float2 o = make_float2(v0, v1);
                    *(float2*)(C + (size_t)row * N + col) = o;
                }
                if (Chi) {
                    __nv_bfloat16 h0 = __float2bfloat16(v0);
                    __nv_bfloat16 h1 = __float2bfloat16(v1);
                    __nv_bfloat162 hp; hp.x = h0; hp.y = h1;
                    *(__nv_bfloat162*)(Chi + (size_t)row * N + col) = hp;
                    __nv_bfloat162 lp;
                    lp.x = __float2bfloat16(v0 - __bfloat162float(h0));
                    lp.y = __float2bfloat16(v1 - __bfloat162float(h1));
                    *(__nv_bfloat162*)(Clo + (size_t)row * N + col) = lp;
                }
            }
        }
    }
}

// ---------------------------------------------------------------------------
// fp32 -> bf16 hi/lo split, vectorized (n divisible by 4)
// ---------------------------------------------------------------------------
__global__ void conv_kernel(const float* __restrict__ s,
                            __nv_bfloat16* __restrict__ hi,
                            __nv_bfloat16* __restrict__ lo, int n)
{
    int i = (blockIdx.x * 256 + threadIdx.x) * 4;
    if (i < n) {
        float4 v = *(const float4*)(s + i);
        __nv_bfloat162 h0, h1, l0, l1;
        h0.x = __float2bfloat16(v.x); h0.y = __float2bfloat16(v.y);
        h1.x = __float2bfloat16(v.z); h1.y = __float2bfloat16(v.w);
        l0.x = __float2bfloat16(v.x - __bfloat162float(h0.x));
        l0.y = __float2bfloat16(v.y - __bfloat162float(h0.y));
        l1.x = __float2bfloat16(v.z - __bfloat162float(h1.x));
        l1.y = __float2bfloat16(v.w - __bfloat162float(h1.y));
        *(__nv_bfloat162*)(hi + i)     = h0;
        *(__nv_bfloat162*)(hi + i + 2) = h1;
        *(__nv_bfloat162*)(lo + i)     = l0;
        *(__nv_bfloat162*)(lo + i + 2) = l1;
    }
}

// init h = concat(x, y), plus hi/lo split (vectorized; MTOK*DD % 4 == 0)
__global__ void hinit_kernel(const float* __restrict__ x,
                             const float* __restrict__ y,
                             float* __restrict__ h,
                             __nv_bfloat16* __restrict__ hi,
                             __nv_bfloat16* __restrict__ lo)
{
    int i = (blockIdx.x * 256 + threadIdx.x) * 4;
    if (i < MT2 * DD) {
        float4 v = (i < MTOK * DD) ? *(const float4*)(x + i)
                                   : *(const float4*)(y + i - MTOK * DD);
        *(float4*)(h + i) = v;
        __nv_bfloat162 h0, h1, l0, l1;
        h0.x = __float2bfloat16(v.x); h0.y = __float2bfloat16(v.y);
        h1.x = __float2bfloat16(v.z); h1.y = __float2bfloat16(v.w);
        l0.x = __float2bfloat16(v.x - __bfloat162float(h0.x));
        l0.y = __float2bfloat16(v.y - __bfloat162float(h0.y));
        l1.x = __float2bfloat16(v.z - __bfloat162float(h1.x));
        l1.y = __float2bfloat16(v.w - __bfloat162float(h1.y));
        *(__nv_bfloat162*)(hi + i)     = h0;
        *(__nv_bfloat162*)(hi + i + 2) = h1;
        *(__nv_bfloat162*)(lo + i)     = l0;
        *(__nv_bfloat162*)(lo + i + 2) = l1;
    }
}

// ---------------------------------------------------------------------------
// Banded attention v2 (|q-k| <= 64), fp32 math. Emits bf16 hi/lo.
// ---------------------------------------------------------------------------
#define KVSTR 68
#define PSTR  161
#define ATTN_SMEM_FLOATS (32 * KVSTR + 160 * KVSTR + 32 * PSTR + 32 * 8)
#define ATTN_SMEM_BYTES  (ATTN_SMEM_FLOATS * 4)   // 73,856 B

__global__ __launch_bounds__(256) void attn_kernel(
    const float* __restrict__ qkv,
    __nv_bfloat16* __restrict__ ohi, __nv_bfloat16* __restrict__ olo)
{
    extern __shared__ float sm[];
    float (*Qs)[KVSTR] = (float(*)[KVSTR])(sm);
    float (*KV)[KVSTR] = (float(*)[KVSTR])(sm + 32 * KVSTR);
    float (*P)[PSTR]   = (float(*)[PSTR])(sm + (32 + 160) * KVSTR);
    float (*red)[8]    = (float(*)[8])(sm + (32 + 160) * KVSTR + 32 * PSTR);
    const uint32_t sQ  = s2u(Qs);
    const uint32_t sKV = s2u(KV);

    const int qt  = blockIdx.x;
    const int hh  = blockIdx.y;
    const int b   = blockIdx.z;
    const int tid = threadIdx.x;
    const int l0  = qt * QT;
    const int k0  = l0 - 64;

    // Phase 1: cp.async Q + K
    {
        int row = tid >> 4, c = tid & 15;
        #pragma unroll
        for (int r2 = 0; r2 < 2; r2++) {
            int rr = row + r2 * 16;
            CPA16(sQ + (uint32_t)(rr * (KVSTR * 4) + c * 16),
                  qkv + ((size_t)(b * LL + l0 + rr)) * (3 * DD) + hh * 64 + c * 4);
        }
        #pragma unroll
        for (int r10 = 0; r10 < 10; r10++) {
            int rr = row + r10 * 16;
            int kg = k0 + rr;
            uint32_t dst = sKV + (uint32_t)(rr * (KVSTR * 4) + c * 16);
            if (kg >= 0 && kg < LL)
                CPA16(dst, qkv + ((size_t)(b * LL + kg)) * (3 * DD) + DD +
                           hh * 64 + c * 4);
            else
                STSZERO(dst);
        }
    }
    CPCOMMIT(); CPWAIT0();
    __syncthreads();

    // Phase 2: scores
    const int q    = tid >> 3;
    const int part = tid & 7;
    const int ql   = l0 + q;
    #pragma unroll 1
    for (int j = 0; j < KW / 8; j++) {
        int kk = part + 8 * j;
        int kg = k0 + kk;
        int dl = ql - kg;
        float s = -1e30f;
        if (kg >= 0 && kg < LL && dl >= -64 && dl <= 64) {
            const float4* qr = (const float4*)Qs[q];
            const float4* kr = (const float4*)KV[kk];
            float dot = 0.f;
            #pragma unroll
            for (int d4 = 0; d4 < 16; d4++) {
                float4 a = qr[d4], kkv = kr[d4];
                dot = fmaf(a.x, kkv.x, dot);
                dot = fmaf(a.y, kkv.y, dot);
                dot = fmaf(a.z, kkv.z, dot);
                dot = fmaf(a.w, kkv.w, dot);
            }
            s = dot * 0.125f;
        }
        P[q][kk] = s;
    }
    __syncthreads();   // scores done; K no longer needed

    // Phase 3a: start V load (overwrites K buffer)
    {
        int row = tid >> 4, c = tid & 15;
        #pragma unroll
        for (int r10 = 0; r10 < 10; r10++) {
            int rr = row + r10 * 16;
            int kg = k0 + rr;
            uint32_t dst = sKV + (uint32_t)(rr * (KVSTR * 4) + c * 16);
            if (kg >= 0 && kg < LL)
                CPA16(dst, qkv + ((size_t)(b * LL + kg)) * (3 * DD) + 2 * DD +
                           hh * 64 + c * 4);
            else
                STSZERO(dst);
        }
    }
    CPCOMMIT();

    // Phase 3b: softmax (overlaps V arrival)
    float m = -1e30f;
    for (int kk = part; kk < KW; kk += 8) m = fmaxf(m, P[q][kk]);
    red[q][part] = m;
    __syncthreads();
    float mq = red[q][0];
    #pragma unroll
    for (int j = 1; j < 8; j++) mq = fmaxf(mq, red[q][j]);
    __syncthreads();
    float ssum = 0.f;
    for (int kk = part; kk < KW; kk += 8) {
        float sc = P[q][kk];
        float e = (sc > -1e29f) ? __expf(sc - mq) : 0.f;
        P[q][kk] = e;
        ssum += e;
    }
    red[q][part] = ssum;
    CPWAIT0();
    __syncthreads();
    float tot = 0.f;
    #pragma unroll
    for (int j = 0; j < 8; j++) tot += red[q][j];
    float rinv = 1.f / tot;

    // Phase 4: P @ V
    float o[8] = {0, 0, 0, 0, 0, 0, 0, 0};
    #pragma unroll 1
    for (int kk = 0; kk < KW; kk++) {
        float p = P[q][kk];
        const float4* vr = (const float4*)&KV[kk][part * 8];
        float4 v0 = vr[0], v1 = vr[1];
        o[0] = fmaf(p, v0.x, o[0]); o[1] = fmaf(p, v0.y, o[1]);
        o[2] = fmaf(p, v0.z, o[2]); o[3] = fmaf(p, v0.w, o[3]);
        o[4] = fmaf(p, v1.x, o[4]); o[5] = fmaf(p, v1.y, o[5]);
        o[6] = fmaf(p, v1.z, o[6]); o[7] = fmaf(p, v1.w, o[7]);
    }
    size_t obase = ((size_t)(b * LL + l0 + q)) * DD + hh * 64 + part * 8;
    #pragma unroll
    for (int d2 = 0; d2 < 8; d2++) {
        float val = o[d2] * rinv;
        __nv_bfloat16 hv = __float2bfloat16(val);
        ohi[obase + d2] = hv;
        olo[obase + d2] = __float2bfloat16(val - __bfloat162float(hv));
    }
}

// ---------------------------------------------------------------------------
// Fused residual add + LayerNorm (in place), optional bf16 hi/lo emission.
// ---------------------------------------------------------------------------
__global__ __launch_bounds__(256) void add_ln_kernel(
    float* __restrict__ h, const float* __restrict__ delta,
    const float* __restrict__ gam, const float* __restrict__ bta, int D,
    __nv_bfloat16* __restrict__ ohi, __nv_bfloat16* __restrict__ olo)
{
    const int row = blockIdx.x;
    const int tid = threadIdx.x;
    float xv[3];
    float s = 0.f, s2 = 0.f;
    #pragma unroll
    for (int j = 0; j < 3; j++) {
        int i = tid + j * 256;
        if (i < D) {
            float v = h[(size_t)row * D + i];
            if (delta) v += delta[(size_t)row * D + i];
            xv[j] = v;
            s += v;
            s2 += v * v;
        }
    }
    __shared__ float rs[8], rs2[8];
    __shared__ float sh_mean, sh_rstd;
    #pragma unroll
    for (int o = 16; o > 0; o >>= 1) {
        s  += __shfl_xor_sync(0xffffffffu, s, o);
        s2 += __shfl_xor_sync(0xffffffffu, s2, o);
    }
    if ((tid & 31) == 0) { rs[tid >> 5] = s; rs2[tid >> 5] = s2; }
    __syncthreads();
    if (tid == 0) {
        float ts = 0.f, ts2 = 0.f;
        #pragma unroll
        for (int w = 0; w < 8; w++) { ts += rs[w]; ts2 += rs2[w]; }
        float mean = ts / (float)D;
        float var = ts2 / (float)D - mean * mean;
        sh_mean = mean;
        sh_rstd = rsqrtf(var + 1e-5f);
    }
    __syncthreads();
    float mean = sh_mean, rstd = sh_rstd;
    #pragma unroll
    for (int j = 0; j < 3; j++) {
        int i = tid + j * 256;
        if (i < D) {
            float v = (xv[j] - mean) * rstd * gam[i] + bta[i];
            h[(size_t)row * D + i] = v;
            if (ohi) {
                __nv_bfloat16 hv = __float2bfloat16(v);
                ohi[(size_t)row * D + i] = hv;
                olo[(size_t)row * D + i] =
                    __float2bfloat16(v - __bfloat162float(hv));
            }
        }
    }
}

// ---------------------------------------------------------------------------
// Pooling, embedding, cosine (2*BB batches)
// ---------------------------------------------------------------------------
__global__ void pool_partial_kernel(const float* __restrict__ h, float* __restrict__ pp)
{
    const int c = blockIdx.x;
    const int b = blockIdx.y;
    for (int d = threadIdx.x; d < DD; d += 256) {
        float a = 0.f;
        int l0 = c * 64;
        for (int l = l0; l < l0 + 64; l++)
            a += h[((size_t)(b * LL + l)) * DD + d];
        pp[(size_t)(b * 16 + c) * DD + d] = a;
    }
}

__global__ void pool_reduce_kernel(const float* __restrict__ pp, float* __restrict__ pool)
{
    const int b = blockIdx.x;
    for (int d = threadIdx.x; d < DD; d += 256) {
        float a = 0.f;
        #pragma unroll
        for (int c = 0; c < 16; c++)
            a += pp[(size_t)(b * 16 + c) * DD + d];
        pool[(size_t)b * DD + d] = a;
    }
}

__global__ __launch_bounds__(256) void embed_kernel(
    const float* __restrict__ e, const float* __restrict__ We,
    const float* __restrict__ be, float* __restrict__ out)
{
    const int b = blockIdx.x;
    __shared__ float es[DD];
    for (int i = threadIdx.x; i < DD; i += 256)
        es[i] = e[(size_t)b * DD + i];
    __syncthreads();
    for (int n = threadIdx.x; n < DD; n += 256) {
        const float4* wr = (const float4*)(We + (size_t)n * DD);
        const float4* er = (const float4*)es;
        float a = 0.f;
        #pragma unroll 4
        for (int d4 = 0; d4 < DD / 4; d4++) {
            float4 w = wr[d4];
            float4 ev = er[d4];
            a = fmaf(w.x, ev.x, a); a = fmaf(w.y, ev.y, a);
            a = fmaf(w.z, ev.z, a); a = fmaf(w.w, ev.w, a);
        }
        a += be[n];
        out[(size_t)b * DD + n] = fmaxf(a, 0.f);
    }
}

__global__ void cos_kernel(const float* __restrict__ e, float* __restrict__ out)
{
    const int w = threadIdx.x >> 5;
    const int lane = threadIdx.x & 31;
    if (w >= BB) return;
    float dot = 0.f, nx2 = 0.f, ny2 = 0.f;
    for (int d = lane; d < DD; d += 32) {
        float a = e[(size_t)w * DD + d];
        float c = e[(size_t)(w + BB) * DD + d];
        dot = fmaf(a, c, dot);
        nx2 = fmaf(a, a, nx2);
        ny2 = fmaf(c, c, ny2);
    }
    #pragma unroll
    for (int o = 16; o > 0; o >>= 1) {
        dot += __shfl_xor_sync(0xffffffffu, dot, o);
        nx2 += __shfl_xor_sync(0xffffffffu, nx2, o);
        ny2 += __shfl_xor_sync(0xffffffffu, ny2, o);
    }
    if (lane == 0) {
        float nx = fmaxf(sqrtf(nx2), 1e-8f);
        float ny = fmaxf(sqrtf(ny2), 1e-8f);
        out[w] = dot / (nx * ny);
    }
}

// ---------------------------------------------------------------------------
// Host orchestration
// ---------------------------------------------------------------------------
static void launch_gemm(const __nv_bfloat16* Ahi, const __nv_bfloat16* Alo,
                        const __nv_bfloat16* Bhi, const __nv_bfloat16* Blo,
                        const float* bias, float* C,
                        __nv_bfloat16* Chi, __nv_bfloat16* Clo,
                        int M, int N, int K, int relu)
{
    dim3 grid(N / 64, M / 128);
    gemm_mma<<<grid, 256, GSMEM>>>(Ahi, Alo, Bhi, Blo, bias, C, Chi, Clo,
                                   M, N, K, relu);
}

extern "C" void kernel_launch(void* const* d_in, const int* in_sizes, int n_in,
                              void* d_out, int out_size)
{
    (void)in_sizes; (void)n_in; (void)out_size;
    const float* x    = (const float*)d_in[0];
    const float* y    = (const float*)d_in[3];
    const float* Wqkv = (const float*)d_in[6];
    const float* bqkv = (const float*)d_in[7];
    const float* Wo   = (const float*)d_in[8];
    const float* bo   = (const float*)d_in[9];
    const float* ln1g = (const float*)d_in[10];
    const float* ln1b = (const float*)d_in[11];
    const float* W1   = (const float*)d_in[12];
    const float* b1   = (const float*)d_in[13];
    const float* W2   = (const float*)d_in[14];
    const float* b2   = (const float*)d_in[15];
    const float* ln2g = (const float*)d_in[16];
    const float* ln2b = (const float*)d_in[17];
    const float* lneg = (const float*)d_in[18];
    const float* lneb = (const float*)d_in[19];
    const float* We   = (const float*)d_in[20];
    const float* be   = (const float*)d_in[21];
    float* out = (float*)d_out;

    float *ph, *pqkv, *pd, *ppp, *ppool, *pe;
    __nv_bfloat16 *phh, *phl, *paoh, *paol, *pf1h, *pf1l;
    __nv_bfloat16 *pwqh, *pwql, *pwoh, *pwol, *pw1h, *pw1l, *pw2h, *pw2l;
    cudaGetSymbolAddress((void**)&ph,    g_h);
    cudaGetSymbolAddress((void**)&pqkv,  g_qkv);
    cudaGetSymbolAddress((void**)&pd,    g_d);
    cudaGetSymbolAddress((void**)&ppp,   g_pp);
    cudaGetSymbolAddress((void**)&ppool, g_pool);
    cudaGetSymbolAddress((void**)&pe,    g_e);
    cudaGetSymbolAddress((void**)&phh,   g_h_hi);
    cudaGetSymbolAddress((void**)&phl,   g_h_lo);
    cudaGetSymbolAddress((void**)&paoh,  g_ao_hi);
    cudaGetSymbolAddress((void**)&paol,  g_ao_lo);
    cudaGetSymbolAddress((void**)&pf1h,  g_f1_hi);
    cudaGetSymbolAddress((void**)&pf1l,  g_f1_lo);
    cudaGetSymbolAddress((void**)&pwqh,  g_wqkv_hi);
    cudaGetSymbolAddress((void**)&pwql,  g_wqkv_lo);
    cudaGetSymbolAddress((void**)&pwoh,  g_wo_hi);
    cudaGetSymbolAddress((void**)&pwol,  g_wo_lo);
    cudaGetSymbolAddress((void**)&pw1h,  g_w1_hi);
    cudaGetSymbolAddress((void**)&pw1l,  g_w1_lo);
    cudaGetSymbolAddress((void**)&pw2h,  g_w2_hi);
    cudaGetSymbolAddress((void**)&pw2l,  g_w2_lo);

    cudaFuncSetAttribute(attn_kernel,
                         cudaFuncAttributeMaxDynamicSharedMemorySize,
                         ATTN_SMEM_BYTES);
    cudaFuncSetAttribute(gemm_mma,
                         cudaFuncAttributeMaxDynamicSharedMemorySize, GSMEM);

    // Launch order keeps gemm_mma (QKV, layer 0) early for ncu capture.
    conv_kernel<<<(WQKV_N / 4 + 255) / 256, 256>>>(Wqkv, pwqh, pwql, WQKV_N);
    conv_kernel<<<(WO_N   / 4 + 255) / 256, 256>>>(Wo,   pwoh, pwol, WO_N);
    hinit_kernel<<<(MT2 * DD / 4 + 255) / 256, 256>>>(x, y, ph, phh, phl);

    for (int l = 0; l < NLAYERS; l++) {
        // QKV projection (fp32 out, consumed by attention)
        launch_gemm(phh, phl,
                    pwqh + (size_t)l * 3 * DD * DD,
                    pwql + (size_t)l * 3 * DD * DD,
                    bqkv + (size_t)l * 3 * DD,
                    pqkv, nullptr, nullptr, MT2, 3 * DD, DD, 0);
        // Banded attention over 16 batched sequences -> bf16 hi/lo
        attn_kernel<<<dim3(LL / QT, HH, 2 * BB), 256, ATTN_SMEM_BYTES>>>(
            pqkv, paoh, paol);
        // Output projection (fp32 out)
        launch_gemm(paoh, paol,
                    pwoh + (size_t)l * DD * DD,
                    pwol + (size_t)l * DD * DD,
                    bo + (size_t)l * DD,
                    pd, nullptr, nullptr, MT2, DD, DD, 0);
        // h = LN(h + attn_proj), emit hi/lo
        add_ln_kernel<<<MT2, 256>>>(ph, pd, ln1g + (size_t)l * DD,
                                    ln1b + (size_t)l * DD, DD, phh, phl);
        // Deferred weight conversion for FF paths (first use is next launch)
        if (l == 0) {
            conv_kernel<<<(W1_N / 4 + 255) / 256, 256>>>(W1, pw1h, pw1l, W1_N);
            conv_kernel<<<(W2_N / 4 + 255) / 256, 256>>>(W2, pw2h, pw2l, W2_N);
        }
        // FF1 + ReLU -> bf16 hi/lo only
        launch_gemm(phh, phl,
                    pw1h + (size_t)l * FFD * DD,
                    pw1l + (size_t)l * FFD * DD,
                    b1 + (size_t)l * FFD,
                    nullptr, pf1h, pf1l, MT2, FFD, DD, 1);
        // FF2 (fp32 out)
        launch_gemm(pf1h, pf1l,
                    pw2h + (size_t)l * DD * FFD,
                    pw2l + (size_t)l * DD * FFD,
                    b2 + (size_t)l * DD,
                    pd, nullptr, nullptr, MT2, DD, FFD, 0);
        // h = LN(h + ff), emit hi/lo
        add_ln_kernel<<<MT2, 256>>>(ph, pd, ln2g + (size_t)l * DD,
                                    ln2b + (size_t)l * DD, DD, phh, phl);
    }

    pool_partial_kernel<<<dim3(16, 2 * BB), 256>>>(ph, ppp);
    pool_reduce_kernel<<<2 * BB, 256>>>(ppp, ppool);
    add_ln_kernel<<<2 * BB, 256>>>(ppool, (const float*)nullptr, lneg, lneb, DD,
                                   nullptr, nullptr);
    embed_kernel<<<2 * BB, 256>>>(ppool, We, be, pe);

    cos_kernel<<<1, 256>>>(pe, out);
}

// round 15
// speedup vs baseline: 1.2793x; 1.2793x over previous
#include <cuda_runtime.h>
#include <cuda_bf16.h>
#include <math.h>
#include <stdint.h>

// Problem constants
#define BB      8
#define LL      1024
#define DD      640
#define HH      10
#define FFD     1280
#define NLAYERS 6
#define MTOK    (BB * LL)      // 8192 tokens per input
#define MT2     (2 * MTOK)     // both inputs batched: 16384 tokens
#define QT      32             // queries per attention block
#define KW      160            // key window per block

// ---------------------------------------------------------------------------
// Static device scratch (both sequences concatenated)
// ---------------------------------------------------------------------------
__device__ float g_h   [MT2 * DD];
__device__ float g_qkv [MT2 * 3 * DD];
__device__ float g_d   [MT2 * DD];
__device__ __nv_bfloat16 g_h_hi [MT2 * DD];
__device__ __nv_bfloat16 g_ao_hi[MT2 * DD];
__device__ __nv_bfloat16 g_f1_hi[MT2 * FFD];

#define WQKV_N (NLAYERS * 3 * DD * DD)
#define WO_N   (NLAYERS * DD * DD)
#define W1_N   (NLAYERS * FFD * DD)
#define W2_N   (NLAYERS * DD * FFD)
__device__ __nv_bfloat16 g_wqkv_hi[WQKV_N], g_wqkv_lo[WQKV_N];
__device__ __nv_bfloat16 g_wo_hi  [WO_N],   g_wo_lo  [WO_N];
__device__ __nv_bfloat16 g_w1_hi  [W1_N],   g_w1_lo  [W1_N];
__device__ __nv_bfloat16 g_w2_hi  [W2_N],   g_w2_lo  [W2_N];

__device__ float g_pp  [2 * BB * 16 * DD];
__device__ float g_pool[2 * BB * DD];
__device__ float g_e   [2 * BB * DD];

// ---------------------------------------------------------------------------
// PTX helpers (non-'a' instructions only: mma.sync / ldmatrix / cp.async)
// ---------------------------------------------------------------------------
__device__ __forceinline__ uint32_t s2u(const void* p) {
    uint32_t a;
    asm("{ .reg .u64 t; cvta.to.shared.u64 t, %1; cvt.u32.u64 %0, t; }"
        : "=r"(a) : "l"(p));
    return a;
}

__device__ __forceinline__ void ldsm4(uint32_t* r, uint32_t addr) {
    asm volatile("ldmatrix.sync.aligned.m8n8.x4.shared.b16 {%0,%1,%2,%3}, [%4];"
                 : "=r"(r[0]), "=r"(r[1]), "=r"(r[2]), "=r"(r[3]) : "r"(addr));
}

__device__ __forceinline__ void mma16816(float* c, const uint32_t* a,
                                         const uint32_t* b) {
    asm volatile(
        "mma.sync.aligned.m16n8k16.row.col.f32.bf16.bf16.f32 "
        "{%0,%1,%2,%3}, {%4,%5,%6,%7}, {%8,%9}, {%0,%1,%2,%3};"
        : "+f"(c[0]), "+f"(c[1]), "+f"(c[2]), "+f"(c[3])
        : "r"(a[0]), "r"(a[1]), "r"(a[2]), "r"(a[3]), "r"(b[0]), "r"(b[1]));
}

#define CPA16(dst, src) \
    asm volatile("cp.async.cg.shared.global [%0], [%1], 16;" \
                 :: "r"(dst), "l"(src))
#define CPCOMMIT() asm volatile("cp.async.commit_group;" ::: "memory")
#define CPWAIT0()  asm volatile("cp.async.wait_group 0;" ::: "memory")
#define STSZERO(dst) \
    asm volatile("st.shared.v4.b32 [%0], {%1,%1,%1,%1};" \
                 :: "r"(dst), "r"(0u) : "memory")

// ---------------------------------------------------------------------------
// mma.sync 2-term split-precision GEMM:
//   C[M,N] = Ahi[M,K] @ (Bhi+Blo)[N,K]^T + bias
// (activation-lo term dropped: tensor pipe is at its mma.sync plateau, so
//  FLOP reduction is the only remaining GEMM lever; weight-lo retained keeps
//  error ~activation-rounding level, est final rel_err ~1e-4.)
// CTA tile 128x64, 256 threads (8 warps, 4x2; warp tile 32x32).
// Stage = 64-wide K slice: Ahi (16KB) + Bhi|Blo (8KB each) = 32KB; double-
// buffered = 64KB -> 3 CTAs/SM. Per kk: 6 ldsm up front, 16 MMAs back-to-back.
// fp32 register accumulation. SMEM rows 128B, xor swizzle chunk ^= row&7.
// ---------------------------------------------------------------------------
#define OPTA  16384                  // A tile: 128 rows x 128B
#define OPTB  8192                   // B tile:  64 rows x 128B
#define SSTG  (OPTA + 2 * OPTB)      // 32KB
#define NSTG  2
#define GSMEM (NSTG * SSTG)          // 64KB

__global__ __launch_bounds__(256, 3) void gemm_mma(
    const __nv_bfloat16* __restrict__ Ahi,
    const __nv_bfloat16* __restrict__ Bhi, const __nv_bfloat16* __restrict__ Blo,
    const float* __restrict__ bias, float* __restrict__ C,
    __nv_bfloat16* __restrict__ Chi,
    int M, int N, int K, int relu)
{
    extern __shared__ char smraw[];
    const uint32_t sb = s2u(smraw);

    const int tid  = threadIdx.x;
    const int wid  = tid >> 5;
    const int lane = tid & 31;
    const int bm   = blockIdx.y * 128;
    const int bn   = blockIdx.x * 64;
    const int wm   = wid >> 1;       // 0..3 (32 rows)
    const int wn   = wid & 1;        // 0..1 (32 cols)

    float acc[2][4][4];
    #pragma unroll
    for (int i = 0; i < 2; i++)
        #pragma unroll
        for (int j = 0; j < 4; j++)
            #pragma unroll
            for (int r = 0; r < 4; r++) acc[i][j][r] = 0.f;

    const int nst = K >> 6;          // 64-wide K slices

    // loader: 8 cp.async/thread: Ahi rows lr0+{0,32,64,96}, B rows lr0+{0,32}
    const int lr0 = tid >> 3;               // 0..31
    const int lc  = tid & 7;                // 16B chunk index 0..7
    const uint32_t swch = (uint32_t)((lc ^ (lr0 & 7)) << 4);  // rows+32k share

    #define LOADSTAGE(S) do {                                               \
        int col = ((S) << 6) + (lc << 3);                                   \
        uint32_t base = sb + ((S) & 1) * SSTG;                              \
        _Pragma("unroll")                                                   \
        for (int i4 = 0; i4 < 4; i4++) {                                    \
            int rr = lr0 + (i4 << 5);                                       \
            uint32_t d = (uint32_t)(rr << 7) + swch;                        \
            CPA16(base + d, Ahi + (size_t)(bm + rr) * K + col);             \
        }                                                                   \
        _Pragma("unroll")                                                   \
        for (int i2 = 0; i2 < 2; i2++) {                                    \
            int rr = lr0 + (i2 << 5);                                       \
            uint32_t d = (uint32_t)(rr << 7) + swch;                        \
            CPA16(base + OPTA + d,                                          \
                  Bhi + (size_t)(bn + rr) * K + col);                       \
            CPA16(base + OPTA + OPTB + d,                                   \
                  Blo + (size_t)(bn + rr) * K + col);                       \
        }                                                                   \
    } while (0)

    // fragment addressing (canonical ldmatrix, swizzled chunks)
    const int lr  = lane & 15;
    const int lh  = lane >> 4;
    const int s7  = lr & 7;
    const uint32_t arow0 = (uint32_t)((wm * 32 +  0 + lr) << 7);
    const uint32_t arow1 = (uint32_t)((wm * 32 + 16 + lr) << 7);
    const uint32_t brow0 = (uint32_t)((wn * 32 +  0 + lr) << 7);
    const uint32_t brow1 = (uint32_t)((wn * 32 + 16 + lr) << 7);

    LOADSTAGE(0); CPCOMMIT();
    CPWAIT0();
    __syncthreads();           // stage 0 visible to all warps

    for (int s = 0; s < nst; s++) {
        // Prefetch s+1 into the buffer consumed in stage s-1 (fully read
        // before the barrier that ended stage s-1).
        if (s + 1 < nst) LOADSTAGE(s + 1);
        CPCOMMIT();            // uniform group accounting

        const uint32_t sS   = sb + (s & 1) * SSTG;
        const uint32_t sAhi = sS;
        const uint32_t sBhi = sS + OPTA;
        const uint32_t sBlo = sS + OPTA + OPTB;

        #pragma unroll
        for (int kk = 0; kk < 4; kk++) {
            const uint32_t chs = (uint32_t)((((kk << 1) | lh) ^ s7) << 4);
            uint32_t ah[2][4];
            uint32_t bh[2][2], bl[2][2], bh2[2][2], bl2[2][2];
            uint32_t r[4];

            // 6 ldsm up front, then 16 MMAs back-to-back
            ldsm4(ah[0], sAhi + arow0 + chs);
            ldsm4(ah[1], sAhi + arow1 + chs);
            ldsm4(r, sBhi + brow0 + chs);
            bh[0][0] = r[0]; bh[0][1] = r[2];
            bh[1][0] = r[1]; bh[1][1] = r[3];
            ldsm4(r, sBlo + brow0 + chs);
            bl[0][0] = r[0]; bl[0][1] = r[2];
            bl[1][0] = r[1]; bl[1][1] = r[3];
            ldsm4(r, sBhi + brow1 + chs);
            bh2[0][0] = r[0]; bh2[0][1] = r[2];
            bh2[1][0] = r[1]; bh2[1][1] = r[3];
            ldsm4(r, sBlo + brow1 + chs);
            bl2[0][0] = r[0]; bl2[0][1] = r[2];
            bl2[1][0] = r[1]; bl2[1][1] = r[3];

            #pragma unroll
            for (int mt = 0; mt < 2; mt++) {
                #pragma unroll
                for (int nt = 0; nt < 2; nt++) {
                    mma16816(acc[mt][nt],     ah[mt], bh[nt]);
                    mma16816(acc[mt][nt],     ah[mt], bl[nt]);
                    mma16816(acc[mt][nt + 2], ah[mt], bh2[nt]);
                    mma16816(acc[mt][nt + 2], ah[mt], bl2[nt]);
                }
            }
        }

        CPWAIT0();             // stage s+1 loads complete
        __syncthreads();       // stage s+1 visible; all warps done with s
    }

    // Epilogue
    const int group = lane >> 2;
    const int tig   = lane & 3;
    #pragma unroll
    for (int mt = 0; mt < 2; mt++) {
        #pragma unroll
        for (int half = 0; half < 2; half++) {
            const int row = bm + wm * 32 + mt * 16 + group + half * 8;
            #pragma unroll
            for (int nt = 0; nt < 4; nt++) {
                const int col = bn + wn * 32 + nt * 8 + tig * 2;
                float v0 = acc[mt][nt][half * 2 + 0] + bias[col];
                float v1 = acc[mt][nt][half * 2 + 1] + bias[col + 1];
                if (relu) { v0 = fmaxf(v0, 0.f); v1 = fmaxf(v1, 0.f); }
                if (C) {
                    float2 o = make_float2(v0, v1);
                    *(float2*)(C + (size_t)row * N + col) = o;
                }
                if (Chi) {
                    __nv_bfloat162 hp;
                    hp.x = __float2bfloat16(v0);
                    hp.y = __float2bfloat16(v1);
                    *(__nv_bfloat162*)(Chi + (size_t)row * N + col) = hp;
                }
            }
        }
    }
}

// ---------------------------------------------------------------------------
// fp32 -> bf16 hi/lo split (weights only), vectorized
// ---------------------------------------------------------------------------
__global__ void conv_kernel(const float* __restrict__ s,
                            __nv_bfloat16* __restrict__ hi,
                            __nv_bfloat16* __restrict__ lo, int n)
{
    int i = (blockIdx.x * 256 + threadIdx.x) * 4;
    if (i < n) {
        float4 v = *(const float4*)(s + i);
        __nv_bfloat162 h0, h1, l0, l1;
        h0.x = __float2bfloat16(v.x); h0.y = __float2bfloat16(v.y);
        h1.x = __float2bfloat16(v.z); h1.y = __float2bfloat16(v.w);
        l0.x = __float2bfloat16(v.x - __bfloat162float(h0.x));
        l0.y = __float2bfloat16(v.y - __bfloat162float(h0.y));
        l1.x = __float2bfloat16(v.z - __bfloat162float(h1.x));
        l1.y = __float2bfloat16(v.w - __bfloat162float(h1.y));
        *(__nv_bfloat162*)(hi + i)     = h0;
        *(__nv_bfloat162*)(hi + i + 2) = h1;
        *(__nv_bfloat162*)(lo + i)     = l0;
        *(__nv_bfloat162*)(lo + i + 2) = l1;
    }
}

// init h = concat(x, y), plus bf16 hi (vectorized; MTOK*DD % 4 == 0)
__global__ void hinit_kernel(const float* __restrict__ x,
                             const float* __restrict__ y,
                             float* __restrict__ h,
                             __nv_bfloat16* __restrict__ hi)
{
    int i = (blockIdx.x * 256 + threadIdx.x) * 4;
    if (i < MT2 * DD) {
        float4 v = (i < MTOK * DD) ? *(const float4*)(x + i)
                                   : *(const float4*)(y + i - MTOK * DD);
        *(float4*)(h + i) = v;
        __nv_bfloat162 h0, h1;
        h0.x = __float2bfloat16(v.x); h0.y = __float2bfloat16(v.y);
        h1.x = __float2bfloat16(v.z); h1.y = __float2bfloat16(v.w);
        *(__nv_bfloat162*)(hi + i)     = h0;
        *(__nv_bfloat162*)(hi + i + 2) = h1;
    }
}

// ---------------------------------------------------------------------------
// Banded attention v2 (|q-k| <= 64), fp32 math. Emits bf16 hi only.
// ---------------------------------------------------------------------------
#define KVSTR 68
#define PSTR  161
#define ATTN_SMEM_FLOATS (32 * KVSTR + 160 * KVSTR + 32 * PSTR + 32 * 8)
#define ATTN_SMEM_BYTES  (ATTN_SMEM_FLOATS * 4)   // 73,856 B

__global__ __launch_bounds__(256) void attn_kernel(
    const float* __restrict__ qkv, __nv_bfloat16* __restrict__ ohi)
{
    extern __shared__ float sm[];
    float (*Qs)[KVSTR] = (float(*)[KVSTR])(sm);
    float (*KV)[KVSTR] = (float(*)[KVSTR])(sm + 32 * KVSTR);
    float (*P)[PSTR]   = (float(*)[PSTR])(sm + (32 + 160) * KVSTR);
    float (*red)[8]    = (float(*)[8])(sm + (32 + 160) * KVSTR + 32 * PSTR);
    const uint32_t sQ  = s2u(Qs);
    const uint32_t sKV = s2u(KV);

    const int qt  = blockIdx.x;
    const int hh  = blockIdx.y;
    const int b   = blockIdx.z;
    const int tid = threadIdx.x;
    const int l0  = qt * QT;
    const int k0  = l0 - 64;

    // Phase 1: cp.async Q + K
    {
        int row = tid >> 4, c = tid & 15;
        #pragma unroll
        for (int r2 = 0; r2 < 2; r2++) {
            int rr = row + r2 * 16;
            CPA16(sQ + (uint32_t)(rr * (KVSTR * 4) + c * 16),
                  qkv + ((size_t)(b * LL + l0 + rr)) * (3 * DD) + hh * 64 + c * 4);
        }
        #pragma unroll
        for (int r10 = 0; r10 < 10; r10++) {
            int rr = row + r10 * 16;
            int kg = k0 + rr;
            uint32_t dst = sKV + (uint32_t)(rr * (KVSTR * 4) + c * 16);
            if (kg >= 0 && kg < LL)
                CPA16(dst, qkv + ((size_t)(b * LL + kg)) * (3 * DD) + DD +
                           hh * 64 + c * 4);
            else
                STSZERO(dst);
        }
    }
    CPCOMMIT(); CPWAIT0();
    __syncthreads();

    // Phase 2: scores
    const int q    = tid >> 3;
    const int part = tid & 7;
    const int ql   = l0 + q;
    #pragma unroll 1
    for (int j = 0; j < KW / 8; j++) {
        int kk = part + 8 * j;
        int kg = k0 + kk;
        int dl = ql - kg;
        float s = -1e30f;
        if (kg >= 0 && kg < LL && dl >= -64 && dl <= 64) {
            const float4* qr = (const float4*)Qs[q];
            const float4* kr = (const float4*)KV[kk];
            float dot = 0.f;
            #pragma unroll
            for (int d4 = 0; d4 < 16; d4++) {
                float4 a = qr[d4], kkv = kr[d4];
                dot = fmaf(a.x, kkv.x, dot);
                dot = fmaf(a.y, kkv.y, dot);
                dot = fmaf(a.z, kkv.z, dot);
                dot = fmaf(a.w, kkv.w, dot);
            }
            s = dot * 0.125f;
        }
        P[q][kk] = s;
    }
    __syncthreads();   // scores done; K no longer needed

    // Phase 3a: start V load (overwrites K buffer)
    {
        int row = tid >> 4, c = tid & 15;
        #pragma unroll
        for (int r10 = 0; r10 < 10; r10++) {
            int rr = row + r10 * 16;
            int kg = k0 + rr;
            uint32_t dst = sKV + (uint32_t)(rr * (KVSTR * 4) + c * 16);
            if (kg >= 0 && kg < LL)
                CPA16(dst, qkv + ((size_t)(b * LL + kg)) * (3 * DD) + 2 * DD +
                           hh * 64 + c * 4);
            else
                STSZERO(dst);
        }
    }
    CPCOMMIT();

    // Phase 3b: softmax (overlaps V arrival)
    float m = -1e30f;
    for (int kk = part; kk < KW; kk += 8) m = fmaxf(m, P[q][kk]);
    red[q][part] = m;
    __syncthreads();
    float mq = red[q][0];
    #pragma unroll
    for (int j = 1; j < 8; j++) mq = fmaxf(mq, red[q][j]);
    __syncthreads();
    float ssum = 0.f;
    for (int kk = part; kk < KW; kk += 8) {
        float sc = P[q][kk];
        float e = (sc > -1e29f) ? __expf(sc - mq) : 0.f;
        P[q][kk] = e;
        ssum += e;
    }
    red[q][part] = ssum;
    CPWAIT0();
    __syncthreads();
    float tot = 0.f;
    #pragma unroll
    for (int j = 0; j < 8; j++) tot += red[q][j];
    float rinv = 1.f / tot;

    // Phase 4: P @ V
    float o[8] = {0, 0, 0, 0, 0, 0, 0, 0};
    #pragma unroll 1
    for (int kk = 0; kk < KW; kk++) {
        float p = P[q][kk];
        const float4* vr = (const float4*)&KV[kk][part * 8];
        float4 v0 = vr[0], v1 = vr[1];
        o[0] = fmaf(p, v0.x, o[0]); o[1] = fmaf(p, v0.y, o[1]);
        o[2] = fmaf(p, v0.z, o[2]); o[3] = fmaf(p, v0.w, o[3]);
        o[4] = fmaf(p, v1.x, o[4]); o[5] = fmaf(p, v1.y, o[5]);
        o[6] = fmaf(p, v1.z, o[6]); o[7] = fmaf(p, v1.w, o[7]);
    }
    size_t obase = ((size_t)(b * LL + l0 + q)) * DD + hh * 64 + part * 8;
    #pragma unroll
    for (int d2 = 0; d2 < 8; d2 += 2) {
        __nv_bfloat162 hp;
        hp.x = __float2bfloat16(o[d2] * rinv);
        hp.y = __float2bfloat16(o[d2 + 1] * rinv);
        *(__nv_bfloat162*)(ohi + obase + d2) = hp;
    }
}

// ---------------------------------------------------------------------------
// Fused residual add + LayerNorm (in place), optional bf16 hi emission.
// ---------------------------------------------------------------------------
__global__ __launch_bounds__(256) void add_ln_kernel(
    float* __restrict__ h, const float* __restrict__ delta,
    const float* __restrict__ gam, const float* __restrict__ bta, int D,
    __nv_bfloat16* __restrict__ ohi)
{
    const int row = blockIdx.x;
    const int tid = threadIdx.x;
    float xv[3];
    float s = 0.f, s2 = 0.f;
    #pragma unroll
    for (int j = 0; j < 3; j++) {
        int i = tid + j * 256;
        if (i < D) {
            float v = h[(size_t)row * D + i];
            if (delta) v += delta[(size_t)row * D + i];
            xv[j] = v;
            s += v;
            s2 += v * v;
        }
    }
    __shared__ float rs[8], rs2[8];
    __shared__ float sh_mean, sh_rstd;
    #pragma unroll
    for (int o = 16; o > 0; o >>= 1) {
        s  += __shfl_xor_sync(0xffffffffu, s, o);
        s2 += __shfl_xor_sync(0xffffffffu, s2, o);
    }
    if ((tid & 31) == 0) { rs[tid >> 5] = s; rs2[tid >> 5] = s2; }
    __syncthreads();
    if (tid == 0) {
        float ts = 0.f, ts2 = 0.f;
        #pragma unroll
        for (int w = 0; w < 8; w++) { ts += rs[w]; ts2 += rs2[w]; }
        float mean = ts / (float)D;
        float var = ts2 / (float)D - mean * mean;
        sh_mean = mean;
        sh_rstd = rsqrtf(var + 1e-5f);
    }
    __syncthreads();
    float mean = sh_mean, rstd = sh_rstd;
    #pragma unroll
    for (int j = 0; j < 3; j++) {
        int i = tid + j * 256;
        if (i < D) {
            float v = (xv[j] - mean) * rstd * gam[i] + bta[i];
            h[(size_t)row * D + i] = v;
            if (ohi)
                ohi[(size_t)row * D + i] = __float2bfloat16(v);
        }
    }
}

// ---------------------------------------------------------------------------
// Pooling, embedding, cosine (2*BB batches)
// ---------------------------------------------------------------------------
__global__ void pool_partial_kernel(const float* __restrict__ h, float* __restrict__ pp)
{
    const int c = blockIdx.x;
    const int b = blockIdx.y;
    for (int d = threadIdx.x; d < DD; d += 256) {
        float a = 0.f;
        int l0 = c * 64;
        for (int l = l0; l < l0 + 64; l++)
            a += h[((size_t)(b * LL + l)) * DD + d];
        pp[(size_t)(b * 16 + c) * DD + d] = a;
    }
}

__global__ void pool_reduce_kernel(const float* __restrict__ pp, float* __restrict__ pool)
{
    const int b = blockIdx.x;
    for (int d = threadIdx.x; d < DD; d += 256) {
        float a = 0.f;
        #pragma unroll
        for (int c = 0; c < 16; c++)
            a += pp[(size_t)(b * 16 + c) * DD + d];
        pool[(size_t)b * DD + d] = a;
    }
}

__global__ __launch_bounds__(256) void embed_kernel(
    const float* __restrict__ e, const float* __restrict__ We,
    const float* __restrict__ be, float* __restrict__ out)
{
    const int b = blockIdx.x;
    __shared__ float es[DD];
    for (int i = threadIdx.x; i < DD; i += 256)
        es[i] = e[(size_t)b * DD + i];
    __syncthreads();
    for (int n = threadIdx.x; n < DD; n += 256) {
        const float4* wr = (const float4*)(We + (size_t)n * DD);
        const float4* er = (const float4*)es;
        float a = 0.f;
        #pragma unroll 4
        for (int d4 = 0; d4 < DD / 4; d4++) {
            float4 w = wr[d4];
            float4 ev = er[d4];
            a = fmaf(w.x, ev.x, a); a = fmaf(w.y, ev.y, a);
            a = fmaf(w.z, ev.z, a); a = fmaf(w.w, ev.w, a);
        }
        a += be[n];
        out[(size_t)b * DD + n] = fmaxf(a, 0.f);
    }
}

__global__ void cos_kernel(const float* __restrict__ e, float* __restrict__ out)
{
    const int w = threadIdx.x >> 5;
    const int lane = threadIdx.x & 31;
    if (w >= BB) return;
    float dot = 0.f, nx2 = 0.f, ny2 = 0.f;
    for (int d = lane; d < DD; d += 32) {
        float a = e[(size_t)w * DD + d];
        float c = e[(size_t)(w + BB) * DD + d];
        dot = fmaf(a, c, dot);
        nx2 = fmaf(a, a, nx2);
        ny2 = fmaf(c, c, ny2);
    }
    #pragma unroll
    for (int o = 16; o > 0; o >>= 1) {
        dot += __shfl_xor_sync(0xffffffffu, dot, o);
        nx2 += __shfl_xor_sync(0xffffffffu, nx2, o);
        ny2 += __shfl_xor_sync(0xffffffffu, ny2, o);
    }
    if (lane == 0) {
        float nx = fmaxf(sqrtf(nx2), 1e-8f);
        float ny = fmaxf(sqrtf(ny2), 1e-8f);
        out[w] = dot / (nx * ny);
    }
}

// ---------------------------------------------------------------------------
// Host orchestration
// ---------------------------------------------------------------------------
static void launch_gemm(const __nv_bfloat16* Ahi,
                        const __nv_bfloat16* Bhi, const __nv_bfloat16* Blo,
                        const float* bias, float* C, __nv_bfloat16* Chi,
                        int M, int N, int K, int relu)
{
    dim3 grid(N / 64, M / 128);
    gemm_mma<<<grid, 256, GSMEM>>>(Ahi, Bhi, Blo, bias, C, Chi, M, N, K, relu);
}

extern "C" void kernel_launch(void* const* d_in, const int* in_sizes, int n_in,
                              void* d_out, int out_size)
{
    (void)in_sizes; (void)n_in; (void)out_size;
    const float* x    = (const float*)d_in[0];
    const float* y    = (const float*)d_in[3];
    const float* Wqkv = (const float*)d_in[6];
    const float* bqkv = (const float*)d_in[7];
    const float* Wo   = (const float*)d_in[8];
    const float* bo   = (const float*)d_in[9];
    const float* ln1g = (const float*)d_in[10];
    const float* ln1b = (const float*)d_in[11];
    const float* W1   = (const float*)d_in[12];
    const float* b1   = (const float*)d_in[13];
    const float* W2   = (const float*)d_in[14];
    const float* b2   = (const float*)d_in[15];
    const float* ln2g = (const float*)d_in[16];
    const float* ln2b = (const float*)d_in[17];
    const float* lneg = (const float*)d_in[18];
    const float* lneb = (const float*)d_in[19];
    const float* We   = (const float*)d_in[20];
    const float* be   = (const float*)d_in[21];
    float* out = (float*)d_out;

    float *ph, *pqkv, *pd, *ppp, *ppool, *pe;
    __nv_bfloat16 *phh, *paoh, *pf1h;
    __nv_bfloat16 *pwqh, *pwql, *pwoh, *pwol, *pw1h, *pw1l, *pw2h, *pw2l;
    cudaGetSymbolAddress((void**)&ph,    g_h);
    cudaGetSymbolAddress((void**)&pqkv,  g_qkv);
    cudaGetSymbolAddress((void**)&pd,    g_d);
    cudaGetSymbolAddress((void**)&ppp,   g_pp);
    cudaGetSymbolAddress((void**)&ppool, g_pool);
    cudaGetSymbolAddress((void**)&pe,    g_e);
    cudaGetSymbolAddress((void**)&phh,   g_h_hi);
    cudaGetSymbolAddress((void**)&paoh,  g_ao_hi);
    cudaGetSymbolAddress((void**)&pf1h,  g_f1_hi);
    cudaGetSymbolAddress((void**)&pwqh,  g_wqkv_hi);
    cudaGetSymbolAddress((void**)&pwql,  g_wqkv_lo);
    cudaGetSymbolAddress((void**)&pwoh,  g_wo_hi);
    cudaGetSymbolAddress((void**)&pwol,  g_wo_lo);
    cudaGetSymbolAddress((void**)&pw1h,  g_w1_hi);
    cudaGetSymbolAddress((void**)&pw1l,  g_w1_lo);
    cudaGetSymbolAddress((void**)&pw2h,  g_w2_hi);
    cudaGetSymbolAddress((void**)&pw2l,  g_w2_lo);

    cudaFuncSetAttribute(attn_kernel,
                         cudaFuncAttributeMaxDynamicSharedMemorySize,
                         ATTN_SMEM_BYTES);
    cudaFuncSetAttribute(gemm_mma,
                         cudaFuncAttributeMaxDynamicSharedMemorySize, GSMEM);

    // Launch order keeps gemm_mma (QKV, layer 0) early for ncu capture.
    conv_kernel<<<(WQKV_N / 4 + 255) / 256, 256>>>(Wqkv, pwqh, pwql, WQKV_N);
    conv_kernel<<<(WO_N   / 4 + 255) / 256, 256>>>(Wo,   pwoh, pwol, WO_N);
    hinit_kernel<<<(MT2 * DD / 4 + 255) / 256, 256>>>(x, y, ph, phh);

    for (int l = 0; l < NLAYERS; l++) {
        // QKV projection (fp32 out, consumed by attention)
        launch_gemm(phh,
                    pwqh + (size_t)l * 3 * DD * DD,
                    pwql + (size_t)l * 3 * DD * DD,
                    bqkv + (size_t)l * 3 * DD,
                    pqkv, nullptr, MT2, 3 * DD, DD, 0);
        // Banded attention over 16 batched sequences -> bf16 hi
        attn_kernel<<<dim3(LL / QT, HH, 2 * BB), 256, ATTN_SMEM_BYTES>>>(
            pqkv, paoh);
        // Output projection (fp32 out)
        launch_gemm(paoh,
                    pwoh + (size_t)l * DD * DD,
                    pwol + (size_t)l * DD * DD,
                    bo + (size_t)l * DD,
                    pd, nullptr, MT2, DD, DD, 0);
        // h = LN(h + attn_proj), emit hi
        add_ln_kernel<<<MT2, 256>>>(ph, pd, ln1g + (size_t)l * DD,
                                    ln1b + (size_t)l * DD, DD, phh);
        // Deferred weight conversion for FF paths (first use is next launch)
        if (l == 0) {
            conv_kernel<<<(W1_N / 4 + 255) / 256, 256>>>(W1, pw1h, pw1l, W1_N);
            conv_kernel<<<(W2_N / 4 + 255) / 256, 256>>>(W2, pw2h, pw2l, W2_N);
        }
        // FF1 + ReLU -> bf16 hi only
        launch_gemm(phh,
                    pw1h + (size_t)l * FFD * DD,
                    pw1l + (size_t)l * FFD * DD,
                    b1 + (size_t)l * FFD,
                    nullptr, pf1h, MT2, FFD, DD, 1);
        // FF2 (fp32 out)
        launch_gemm(pf1h,
                    pw2h + (size_t)l * DD * FFD,
                    pw2l + (size_t)l * DD * FFD,
                    b2 + (size_t)l * DD,
                    pd, nullptr, MT2, DD, FFD, 0);
        // h = LN(h + ff), emit hi
        add_ln_kernel<<<MT2, 256>>>(ph, pd, ln2g + (size_t)l * DD,
                                    ln2b + (size_t)l * DD, DD, phh);
    }

    pool_partial_kernel<<<dim3(16, 2 * BB), 256>>>(ph, ppp);
    pool_reduce_kernel<<<2 * BB, 256>>>(ppp, ppool);
    add_ln_kernel<<<2 * BB, 256>>>(ppool, (const float*)nullptr, lneg, lneb, DD,
                                   nullptr);
    embed_kernel<<<2 * BB, 256>>>(ppool, We, be, pe);

    cos_kernel<<<1, 256>>>(pe, out);
}

// round 16
// speedup vs baseline: 1.5330x; 1.1983x over previous
#include <cuda_runtime.h>
#include <cuda_bf16.h>
#include <math.h>
#include <stdint.h>

// Problem constants
#define BB      8
#define LL      1024
#define DD      640
#define HH      10
#define FFD     1280
#define NLAYERS 6
#define MTOK    (BB * LL)      // 8192 tokens per input
#define MT2     (2 * MTOK)     // both inputs batched: 16384 tokens
#define QT      32             // queries per attention block
#define KW      160            // key window per block

// ---------------------------------------------------------------------------
// Static device scratch (both sequences concatenated)
// ---------------------------------------------------------------------------
__device__ float g_h   [MT2 * DD];
__device__ float g_qkv [MT2 * 3 * DD];
__device__ float g_d   [MT2 * DD];
__device__ __nv_bfloat16 g_h_hi [MT2 * DD];
__device__ __nv_bfloat16 g_ao_hi[MT2 * DD];
__device__ __nv_bfloat16 g_f1_hi[MT2 * FFD];

#define WQKV_N (NLAYERS * 3 * DD * DD)
#define WO_N   (NLAYERS * DD * DD)
#define W1_N   (NLAYERS * FFD * DD)
#define W2_N   (NLAYERS * DD * FFD)
__device__ __nv_bfloat16 g_wqkv_hi[WQKV_N];
__device__ __nv_bfloat16 g_wo_hi  [WO_N];
__device__ __nv_bfloat16 g_w1_hi  [W1_N];
__device__ __nv_bfloat16 g_w2_hi  [W2_N];

__device__ float g_pp  [2 * BB * 16 * DD];
__device__ float g_pool[2 * BB * DD];
__device__ float g_e   [2 * BB * DD];

// ---------------------------------------------------------------------------
// PTX helpers (non-'a' instructions only: mma.sync / ldmatrix / cp.async)
// ---------------------------------------------------------------------------
__device__ __forceinline__ uint32_t s2u(const void* p) {
    uint32_t a;
    asm("{ .reg .u64 t; cvta.to.shared.u64 t, %1; cvt.u32.u64 %0, t; }"
        : "=r"(a) : "l"(p));
    return a;
}

__device__ __forceinline__ void ldsm4(uint32_t* r, uint32_t addr) {
    asm volatile("ldmatrix.sync.aligned.m8n8.x4.shared.b16 {%0,%1,%2,%3}, [%4];"
                 : "=r"(r[0]), "=r"(r[1]), "=r"(r[2]), "=r"(r[3]) : "r"(addr));
}

__device__ __forceinline__ void mma16816(float* c, const uint32_t* a,
                                         const uint32_t* b) {
    asm volatile(
        "mma.sync.aligned.m16n8k16.row.col.f32.bf16.bf16.f32 "
        "{%0,%1,%2,%3}, {%4,%5,%6,%7}, {%8,%9}, {%0,%1,%2,%3};"
        : "+f"(c[0]), "+f"(c[1]), "+f"(c[2]), "+f"(c[3])
        : "r"(a[0]), "r"(a[1]), "r"(a[2]), "r"(a[3]), "r"(b[0]), "r"(b[1]));
}

#define CPA16(dst, src) \
    asm volatile("cp.async.cg.shared.global [%0], [%1], 16;" \
                 :: "r"(dst), "l"(src))
#define CPCOMMIT() asm volatile("cp.async.commit_group;" ::: "memory")
#define CPWAIT0()  asm volatile("cp.async.wait_group 0;" ::: "memory")
#define STSZERO(dst) \
    asm volatile("st.shared.v4.b32 [%0], {%1,%1,%1,%1};" \
                 :: "r"(dst), "r"(0u) : "memory")

// ---------------------------------------------------------------------------
// Pure-bf16 mma.sync GEMM:  C[M,N] = Ahi[M,K] @ Bhi[N,K]^T + bias
// (both lo terms dropped: empirically calibrated — the 2-term drop moved
//  rel_err only 1.5e-7 -> 1.9e-6, so weight rounding adds a comparable
//  ~2e-6; tensor pipe is at the mma.sync plateau so time ~ MMA count.)
// CTA tile 128x64, 256 threads (8 warps, 4x2; warp tile 32x32).
// Stage = 64-wide K slice: Ahi 16KB + Bhi 8KB = 24KB; double-buffered =
// 48KB -> 3 CTAs/SM. Per kk: 4 ldsm up front, 8 MMAs back-to-back.
// fp32 register accumulation. SMEM rows 128B, xor swizzle chunk ^= row&7.
// ---------------------------------------------------------------------------
#define OPTA  16384                  // A tile: 128 rows x 128B
#define OPTB  8192                   // B tile:  64 rows x 128B
#define SSTG  (OPTA + OPTB)          // 24KB
#define NSTG  2
#define GSMEM (NSTG * SSTG)          // 48KB

__global__ __launch_bounds__(256, 3) void gemm_mma(
    const __nv_bfloat16* __restrict__ Ahi,
    const __nv_bfloat16* __restrict__ Bhi,
    const float* __restrict__ bias, float* __restrict__ C,
    __nv_bfloat16* __restrict__ Chi,
    int M, int N, int K, int relu)
{
    extern __shared__ char smraw[];
    const uint32_t sb = s2u(smraw);

    const int tid  = threadIdx.x;
    const int wid  = tid >> 5;
    const int lane = tid & 31;
    const int bm   = blockIdx.y * 128;
    const int bn   = blockIdx.x * 64;
    const int wm   = wid >> 1;       // 0..3 (32 rows)
    const int wn   = wid & 1;        // 0..1 (32 cols)

    float acc[2][4][4];
    #pragma unroll
    for (int i = 0; i < 2; i++)
        #pragma unroll
        for (int j = 0; j < 4; j++)
            #pragma unroll
            for (int r = 0; r < 4; r++) acc[i][j][r] = 0.f;

    const int nst = K >> 6;          // 64-wide K slices

    // loader: 6 cp.async/thread: A rows lr0+{0,32,64,96}, B rows lr0+{0,32}
    const int lr0 = tid >> 3;               // 0..31
    const int lc  = tid & 7;                // 16B chunk index 0..7
    const uint32_t swch = (uint32_t)((lc ^ (lr0 & 7)) << 4);  // rows+32k share

    #define LOADSTAGE(S) do {                                               \
        int col = ((S) << 6) + (lc << 3);                                   \
        uint32_t base = sb + ((S) & 1) * SSTG;                              \
        _Pragma("unroll")                                                   \
        for (int i4 = 0; i4 < 4; i4++) {                                    \
            int rr = lr0 + (i4 << 5);                                       \
            uint32_t d = (uint32_t)(rr << 7) + swch;                        \
            CPA16(base + d, Ahi + (size_t)(bm + rr) * K + col);             \
        }                                                                   \
        _Pragma("unroll")                                                   \
        for (int i2 = 0; i2 < 2; i2++) {                                    \
            int rr = lr0 + (i2 << 5);                                       \
            uint32_t d = (uint32_t)(rr << 7) + swch;                        \
            CPA16(base + OPTA + d, Bhi + (size_t)(bn + rr) * K + col);      \
        }                                                                   \
    } while (0)

    // fragment addressing (canonical ldmatrix, swizzled chunks)
    const int lr  = lane & 15;
    const int lh  = lane >> 4;
    const int s7  = lr & 7;
    const uint32_t arow0 = (uint32_t)((wm * 32 +  0 + lr) << 7);
    const uint32_t arow1 = (uint32_t)((wm * 32 + 16 + lr) << 7);
    const uint32_t brow0 = (uint32_t)((wn * 32 +  0 + lr) << 7);
    const uint32_t brow1 = (uint32_t)((wn * 32 + 16 + lr) << 7);

    LOADSTAGE(0); CPCOMMIT();
    CPWAIT0();
    __syncthreads();           // stage 0 visible to all warps

    for (int s = 0; s < nst; s++) {
        // Prefetch s+1 into the buffer consumed in stage s-1 (fully read
        // before the barrier that ended stage s-1).
        if (s + 1 < nst) LOADSTAGE(s + 1);
        CPCOMMIT();            // uniform group accounting

        const uint32_t sS   = sb + (s & 1) * SSTG;
        const uint32_t sAhi = sS;
        const uint32_t sBhi = sS + OPTA;

        #pragma unroll
        for (int kk = 0; kk < 4; kk++) {
            const uint32_t chs = (uint32_t)((((kk << 1) | lh) ^ s7) << 4);
            uint32_t ah[2][4];
            uint32_t bh[2][2], bh2[2][2];
            uint32_t r[4];

            // 4 ldsm up front, then 8 MMAs back-to-back
            ldsm4(ah[0], sAhi + arow0 + chs);
            ldsm4(ah[1], sAhi + arow1 + chs);
            ldsm4(r, sBhi + brow0 + chs);
            bh[0][0] = r[0]; bh[0][1] = r[2];
            bh[1][0] = r[1]; bh[1][1] = r[3];
            ldsm4(r, sBhi + brow1 + chs);
            bh2[0][0] = r[0]; bh2[0][1] = r[2];
            bh2[1][0] = r[1]; bh2[1][1] = r[3];

            #pragma unroll
            for (int mt = 0; mt < 2; mt++) {
                #pragma unroll
                for (int nt = 0; nt < 2; nt++) {
                    mma16816(acc[mt][nt],     ah[mt], bh[nt]);
                    mma16816(acc[mt][nt + 2], ah[mt], bh2[nt]);
                }
            }
        }

        CPWAIT0();             // stage s+1 loads complete
        __syncthreads();       // stage s+1 visible; all warps done with s
    }

    // Epilogue
    const int group = lane >> 2;
    const int tig   = lane & 3;
    #pragma unroll
    for (int mt = 0; mt < 2; mt++) {
        #pragma unroll
        for (int half = 0; half < 2; half++) {
            const int row = bm + wm * 32 + mt * 16 + group + half * 8;
            #pragma unroll
            for (int nt = 0; nt < 4; nt++) {
                const int col = bn + wn * 32 + nt * 8 + tig * 2;
                float v0 = acc[mt][nt][half * 2 + 0] + bias[col];
                float v1 = acc[mt][nt][half * 2 + 1] + bias[col + 1];
                if (relu) { v0 = fmaxf(v0, 0.f); v1 = fmaxf(v1, 0.f); }
                if (C) {
                    float2 o = make_float2(v0, v1);
                    *(float2*)(C + (size_t)row * N + col) = o;
                }
                if (Chi) {
                    __nv_bfloat162 hp;
                    hp.x = __float2bfloat16(v0);
                    hp.y = __float2bfloat16(v1);
                    *(__nv_bfloat162*)(Chi + (size_t)row * N + col) = hp;
                }
            }
        }
    }
}

// ---------------------------------------------------------------------------
// fp32 -> bf16 (weights), vectorized
// ---------------------------------------------------------------------------
__global__ void conv_kernel(const float* __restrict__ s,
                            __nv_bfloat16* __restrict__ hi, int n)
{
    int i = (blockIdx.x * 256 + threadIdx.x) * 4;
    if (i < n) {
        float4 v = *(const float4*)(s + i);
        __nv_bfloat162 h0, h1;
        h0.x = __float2bfloat16(v.x); h0.y = __float2bfloat16(v.y);
        h1.x = __float2bfloat16(v.z); h1.y = __float2bfloat16(v.w);
        *(__nv_bfloat162*)(hi + i)     = h0;
        *(__nv_bfloat162*)(hi + i + 2) = h1;
    }
}

// init h = concat(x, y), plus bf16 hi (vectorized; MTOK*DD % 4 == 0)
__global__ void hinit_kernel(const float* __restrict__ x,
                             const float* __restrict__ y,
                             float* __restrict__ h,
                             __nv_bfloat16* __restrict__ hi)
{
    int i = (blockIdx.x * 256 + threadIdx.x) * 4;
    if (i < MT2 * DD) {
        float4 v = (i < MTOK * DD) ? *(const float4*)(x + i)
                                   : *(const float4*)(y + i - MTOK * DD);
        *(float4*)(h + i) = v;
        __nv_bfloat162 h0, h1;
        h0.x = __float2bfloat16(v.x); h0.y = __float2bfloat16(v.y);
        h1.x = __float2bfloat16(v.z); h1.y = __float2bfloat16(v.w);
        *(__nv_bfloat162*)(hi + i)     = h0;
        *(__nv_bfloat162*)(hi + i + 2) = h1;
    }
}

// ---------------------------------------------------------------------------
// Banded attention v2 (|q-k| <= 64), fp32 math. Emits bf16 hi only.
// ---------------------------------------------------------------------------
#define KVSTR 68
#define PSTR  161
#define ATTN_SMEM_FLOATS (32 * KVSTR + 160 * KVSTR + 32 * PSTR + 32 * 8)
#define ATTN_SMEM_BYTES  (ATTN_SMEM_FLOATS * 4)   // 73,856 B

__global__ __launch_bounds__(256) void attn_kernel(
    const float* __restrict__ qkv, __nv_bfloat16* __restrict__ ohi)
{
    extern __shared__ float sm[];
    float (*Qs)[KVSTR] = (float(*)[KVSTR])(sm);
    float (*KV)[KVSTR] = (float(*)[KVSTR])(sm + 32 * KVSTR);
    float (*P)[PSTR]   = (float(*)[PSTR])(sm + (32 + 160) * KVSTR);
    float (*red)[8]    = (float(*)[8])(sm + (32 + 160) * KVSTR + 32 * PSTR);
    const uint32_t sQ  = s2u(Qs);
    const uint32_t sKV = s2u(KV);

    const int qt  = blockIdx.x;
    const int hh  = blockIdx.y;
    const int b   = blockIdx.z;
    const int tid = threadIdx.x;
    const int l0  = qt * QT;
    const int k0  = l0 - 64;

    // Phase 1: cp.async Q + K
    {
        int row = tid >> 4, c = tid & 15;
        #pragma unroll
        for (int r2 = 0; r2 < 2; r2++) {
            int rr = row + r2 * 16;
            CPA16(sQ + (uint32_t)(rr * (KVSTR * 4) + c * 16),
                  qkv + ((size_t)(b * LL + l0 + rr)) * (3 * DD) + hh * 64 + c * 4);
        }
        #pragma unroll
        for (int r10 = 0; r10 < 10; r10++) {
            int rr = row + r10 * 16;
            int kg = k0 + rr;
            uint32_t dst = sKV + (uint32_t)(rr * (KVSTR * 4) + c * 16);
            if (kg >= 0 && kg < LL)
                CPA16(dst, qkv + ((size_t)(b * LL + kg)) * (3 * DD) + DD +
                           hh * 64 + c * 4);
            else
                STSZERO(dst);
        }
    }
    CPCOMMIT(); CPWAIT0();
    __syncthreads();

    // Phase 2: scores
    const int q    = tid >> 3;
    const int part = tid & 7;
    const int ql   = l0 + q;
    #pragma unroll 1
    for (int j = 0; j < KW / 8; j++) {
        int kk = part + 8 * j;
        int kg = k0 + kk;
        int dl = ql - kg;
        float s = -1e30f;
        if (kg >= 0 && kg < LL && dl >= -64 && dl <= 64) {
            const float4* qr = (const float4*)Qs[q];
            const float4* kr = (const float4*)KV[kk];
            float dot = 0.f;
            #pragma unroll
            for (int d4 = 0; d4 < 16; d4++) {
                float4 a = qr[d4], kkv = kr[d4];
                dot = fmaf(a.x, kkv.x, dot);
                dot = fmaf(a.y, kkv.y, dot);
                dot = fmaf(a.z, kkv.z, dot);
                dot = fmaf(a.w, kkv.w, dot);
            }
            s = dot * 0.125f;
        }
        P[q][kk] = s;
    }
    __syncthreads();   // scores done; K no longer needed

    // Phase 3a: start V load (overwrites K buffer)
    {
        int row = tid >> 4, c = tid & 15;
        #pragma unroll
        for (int r10 = 0; r10 < 10; r10++) {
            int rr = row + r10 * 16;
            int kg = k0 + rr;
            uint32_t dst = sKV + (uint32_t)(rr * (KVSTR * 4) + c * 16);
            if (kg >= 0 && kg < LL)
                CPA16(dst, qkv + ((size_t)(b * LL + kg)) * (3 * DD) + 2 * DD +
                           hh * 64 + c * 4);
            else
                STSZERO(dst);
        }
    }
    CPCOMMIT();

    // Phase 3b: softmax (overlaps V arrival)
    float m = -1e30f;
    for (int kk = part; kk < KW; kk += 8) m = fmaxf(m, P[q][kk]);
    red[q][part] = m;
    __syncthreads();
    float mq = red[q][0];
    #pragma unroll
    for (int j = 1; j < 8; j++) mq = fmaxf(mq, red[q][j]);
    __syncthreads();
    float ssum = 0.f;
    for (int kk = part; kk < KW; kk += 8) {
        float sc = P[q][kk];
        float e = (sc > -1e29f) ? __expf(sc - mq) : 0.f;
        P[q][kk] = e;
        ssum += e;
    }
    red[q][part] = ssum;
    CPWAIT0();
    __syncthreads();
    float tot = 0.f;
    #pragma unroll
    for (int j = 0; j < 8; j++) tot += red[q][j];
    float rinv = 1.f / tot;

    // Phase 4: P @ V
    float o[8] = {0, 0, 0, 0, 0, 0, 0, 0};
    #pragma unroll 1
    for (int kk = 0; kk < KW; kk++) {
        float p = P[q][kk];
        const float4* vr = (const float4*)&KV[kk][part * 8];
        float4 v0 = vr[0], v1 = vr[1];
        o[0] = fmaf(p, v0.x, o[0]); o[1] = fmaf(p, v0.y, o[1]);
        o[2] = fmaf(p, v0.z, o[2]); o[3] = fmaf(p, v0.w, o[3]);
        o[4] = fmaf(p, v1.x, o[4]); o[5] = fmaf(p, v1.y, o[5]);
        o[6] = fmaf(p, v1.z, o[6]); o[7] = fmaf(p, v1.w, o[7]);
    }
    size_t obase = ((size_t)(b * LL + l0 + q)) * DD + hh * 64 + part * 8;
    #pragma unroll
    for (int d2 = 0; d2 < 8; d2 += 2) {
        __nv_bfloat162 hp;
        hp.x = __float2bfloat16(o[d2] * rinv);
        hp.y = __float2bfloat16(o[d2 + 1] * rinv);
        *(__nv_bfloat162*)(ohi + obase + d2) = hp;
    }
}

// ---------------------------------------------------------------------------
// Fused residual add + LayerNorm (in place), optional bf16 hi emission.
// ---------------------------------------------------------------------------
__global__ __launch_bounds__(256) void add_ln_kernel(
    float* __restrict__ h, const float* __restrict__ delta,
    const float* __restrict__ gam, const float* __restrict__ bta, int D,
    __nv_bfloat16* __restrict__ ohi)
{
    const int row = blockIdx.x;
    const int tid = threadIdx.x;
    float xv[3];
    float s = 0.f, s2 = 0.f;
    #pragma unroll
    for (int j = 0; j < 3; j++) {
        int i = tid + j * 256;
        if (i < D) {
            float v = h[(size_t)row * D + i];
            if (delta) v += delta[(size_t)row * D + i];
            xv[j] = v;
            s += v;
            s2 += v * v;
        }
    }
    __shared__ float rs[8], rs2[8];
    __shared__ float sh_mean, sh_rstd;
    #pragma unroll
    for (int o = 16; o > 0; o >>= 1) {
        s  += __shfl_xor_sync(0xffffffffu, s, o);
        s2 += __shfl_xor_sync(0xffffffffu, s2, o);
    }
    if ((tid & 31) == 0) { rs[tid >> 5] = s; rs2[tid >> 5] = s2; }
    __syncthreads();
    if (tid == 0) {
        float ts = 0.f, ts2 = 0.f;
        #pragma unroll
        for (int w = 0; w < 8; w++) { ts += rs[w]; ts2 += rs2[w]; }
        float mean = ts / (float)D;
        float var = ts2 / (float)D - mean * mean;
        sh_mean = mean;
        sh_rstd = rsqrtf(var + 1e-5f);
    }
    __syncthreads();
    float mean = sh_mean, rstd = sh_rstd;
    #pragma unroll
    for (int j = 0; j < 3; j++) {
        int i = tid + j * 256;
        if (i < D) {
            float v = (xv[j] - mean) * rstd * gam[i] + bta[i];
            h[(size_t)row * D + i] = v;
            if (ohi)
                ohi[(size_t)row * D + i] = __float2bfloat16(v);
        }
    }
}

// ---------------------------------------------------------------------------
// Pooling, embedding, cosine (2*BB batches)
// ---------------------------------------------------------------------------
__global__ void pool_partial_kernel(const float* __restrict__ h, float* __restrict__ pp)
{
    const int c = blockIdx.x;
    const int b = blockIdx.y;
    for (int d = threadIdx.x; d < DD; d += 256) {
        float a = 0.f;
        int l0 = c * 64;
        for (int l = l0; l < l0 + 64; l++)
            a += h[((size_t)(b * LL + l)) * DD + d];
        pp[(size_t)(b * 16 + c) * DD + d] = a;
    }
}

__global__ void pool_reduce_kernel(const float* __restrict__ pp, float* __restrict__ pool)
{
    const int b = blockIdx.x;
    for (int d = threadIdx.x; d < DD; d += 256) {
        float a = 0.f;
        #pragma unroll
        for (int c = 0; c < 16; c++)
            a += pp[(size_t)(b * 16 + c) * DD + d];
        pool[(size_t)b * DD + d] = a;
    }
}

__global__ __launch_bounds__(256) void embed_kernel(
    const float* __restrict__ e, const float* __restrict__ We,
    const float* __restrict__ be, float* __restrict__ out)
{
    const int b = blockIdx.x;
    __shared__ float es[DD];
    for (int i = threadIdx.x; i < DD; i += 256)
        es[i] = e[(size_t)b * DD + i];
    __syncthreads();
    for (int n = threadIdx.x; n < DD; n += 256) {
        const float4* wr = (const float4*)(We + (size_t)n * DD);
        const float4* er = (const float4*)es;
        float a = 0.f;
        #pragma unroll 4
        for (int d4 = 0; d4 < DD / 4; d4++) {
            float4 w = wr[d4];
            float4 ev = er[d4];
            a = fmaf(w.x, ev.x, a); a = fmaf(w.y, ev.y, a);
            a = fmaf(w.z, ev.z, a); a = fmaf(w.w, ev.w, a);
        }
        a += be[n];
        out[(size_t)b * DD + n] = fmaxf(a, 0.f);
    }
}

__global__ void cos_kernel(const float* __restrict__ e, float* __restrict__ out)
{
    const int w = threadIdx.x >> 5;
    const int lane = threadIdx.x & 31;
    if (w >= BB) return;
    float dot = 0.f, nx2 = 0.f, ny2 = 0.f;
    for (int d = lane; d < DD; d += 32) {
        float a = e[(size_t)w * DD + d];
        float c = e[(size_t)(w + BB) * DD + d];
        dot = fmaf(a, c, dot);
        nx2 = fmaf(a, a, nx2);
        ny2 = fmaf(c, c, ny2);
    }
    #pragma unroll
    for (int o = 16; o > 0; o >>= 1) {
        dot += __shfl_xor_sync(0xffffffffu, dot, o);
        nx2 += __shfl_xor_sync(0xffffffffu, nx2, o);
        ny2 += __shfl_xor_sync(0xffffffffu, ny2, o);
    }
    if (lane == 0) {
        float nx = fmaxf(sqrtf(nx2), 1e-8f);
        float ny = fmaxf(sqrtf(ny2), 1e-8f);
        out[w] = dot / (nx * ny);
    }
}

// ---------------------------------------------------------------------------
// Host orchestration
// ---------------------------------------------------------------------------
static void launch_gemm(const __nv_bfloat16* Ahi, const __nv_bfloat16* Bhi,
                        const float* bias, float* C, __nv_bfloat16* Chi,
                        int M, int N, int K, int relu)
{
    dim3 grid(N / 64, M / 128);
    gemm_mma<<<grid, 256, GSMEM>>>(Ahi, Bhi, bias, C, Chi, M, N, K, relu);
}

extern "C" void kernel_launch(void* const* d_in, const int* in_sizes, int n_in,
                              void* d_out, int out_size)
{
    (void)in_sizes; (void)n_in; (void)out_size;
    const float* x    = (const float*)d_in[0];
    const float* y    = (const float*)d_in[3];
    const float* Wqkv = (const float*)d_in[6];
    const float* bqkv = (const float*)d_in[7];
    const float* Wo   = (const float*)d_in[8];
    const float* bo   = (const float*)d_in[9];
    const float* ln1g = (const float*)d_in[10];
    const float* ln1b = (const float*)d_in[11];
    const float* W1   = (const float*)d_in[12];
    const float* b1   = (const float*)d_in[13];
    const float* W2   = (const float*)d_in[14];
    const float* b2   = (const float*)d_in[15];
    const float* ln2g = (const float*)d_in[16];
    const float* ln2b = (const float*)d_in[17];
    const float* lneg = (const float*)d_in[18];
    const float* lneb = (const float*)d_in[19];
    const float* We   = (const float*)d_in[20];
    const float* be   = (const float*)d_in[21];
    float* out = (float*)d_out;

    float *ph, *pqkv, *pd, *ppp, *ppool, *pe;
    __nv_bfloat16 *phh, *paoh, *pf1h;
    __nv_bfloat16 *pwqh, *pwoh, *pw1h, *pw2h;
    cudaGetSymbolAddress((void**)&ph,    g_h);
    cudaGetSymbolAddress((void**)&pqkv,  g_qkv);
    cudaGetSymbolAddress((void**)&pd,    g_d);
    cudaGetSymbolAddress((void**)&ppp,   g_pp);
    cudaGetSymbolAddress((void**)&ppool, g_pool);
    cudaGetSymbolAddress((void**)&pe,    g_e);
    cudaGetSymbolAddress((void**)&phh,   g_h_hi);
    cudaGetSymbolAddress((void**)&paoh,  g_ao_hi);
    cudaGetSymbolAddress((void**)&pf1h,  g_f1_hi);
    cudaGetSymbolAddress((void**)&pwqh,  g_wqkv_hi);
    cudaGetSymbolAddress((void**)&pwoh,  g_wo_hi);
    cudaGetSymbolAddress((void**)&pw1h,  g_w1_hi);
    cudaGetSymbolAddress((void**)&pw2h,  g_w2_hi);

    cudaFuncSetAttribute(attn_kernel,
                         cudaFuncAttributeMaxDynamicSharedMemorySize,
                         ATTN_SMEM_BYTES);
    cudaFuncSetAttribute(gemm_mma,
                         cudaFuncAttributeMaxDynamicSharedMemorySize, GSMEM);

    // Launch order keeps gemm_mma (QKV, layer 0) early for ncu capture.
    conv_kernel<<<(WQKV_N / 4 + 255) / 256, 256>>>(Wqkv, pwqh, WQKV_N);
    conv_kernel<<<(WO_N   / 4 + 255) / 256, 256>>>(Wo,   pwoh, WO_N);
    hinit_kernel<<<(MT2 * DD / 4 + 255) / 256, 256>>>(x, y, ph, phh);

    for (int l = 0; l < NLAYERS; l++) {
        // QKV projection (fp32 out, consumed by attention)
        launch_gemm(phh,
                    pwqh + (size_t)l * 3 * DD * DD,
                    bqkv + (size_t)l * 3 * DD,
                    pqkv, nullptr, MT2, 3 * DD, DD, 0);
        // Banded attention over 16 batched sequences -> bf16 hi
        attn_kernel<<<dim3(LL / QT, HH, 2 * BB), 256, ATTN_SMEM_BYTES>>>(
            pqkv, paoh);
        // Output projection (fp32 out)
        launch_gemm(paoh,
                    pwoh + (size_t)l * DD * DD,
                    bo + (size_t)l * DD,
                    pd, nullptr, MT2, DD, DD, 0);
        // h = LN(h + attn_proj), emit hi
        add_ln_kernel<<<MT2, 256>>>(ph, pd, ln1g + (size_t)l * DD,
                                    ln1b + (size_t)l * DD, DD, phh);
        // Deferred weight conversion for FF paths (first use is next launch)
        if (l == 0) {
            conv_kernel<<<(W1_N / 4 + 255) / 256, 256>>>(W1, pw1h, W1_N);
            conv_kernel<<<(W2_N / 4 + 255) / 256, 256>>>(W2, pw2h, W2_N);
        }
        // FF1 + ReLU -> bf16 hi only
        launch_gemm(phh,
                    pw1h + (size_t)l * FFD * DD,
                    b1 + (size_t)l * FFD,
                    nullptr, pf1h, MT2, FFD, DD, 1);
        // FF2 (fp32 out)
        launch_gemm(pf1h,
                    pw2h + (size_t)l * DD * FFD,
                    b2 + (size_t)l * DD,
                    pd, nullptr, MT2, DD, FFD, 0);
        // h = LN(h + ff), emit hi
        add_ln_kernel<<<MT2, 256>>>(ph, pd, ln2g + (size_t)l * DD,
                                    ln2b + (size_t)l * DD, DD, phh);
    }

    pool_partial_kernel<<<dim3(16, 2 * BB), 256>>>(ph, ppp);
    pool_reduce_kernel<<<2 * BB, 256>>>(ppp, ppool);
    add_ln_kernel<<<2 * BB, 256>>>(ppool, (const float*)nullptr, lneg, lneb, DD,
                                   nullptr);
    embed_kernel<<<2 * BB, 256>>>(ppool, We, be, pe);

    cos_kernel<<<1, 256>>>(pe, out);
}

// round 17
// speedup vs baseline: 2.1243x; 1.3857x over previous
#include <cuda_runtime.h>
#include <cuda_bf16.h>
#include <math.h>
#include <stdint.h>

// Problem constants
#define BB      8
#define LL      1024
#define DD      640
#define HH      10
#define FFD     1280
#define NLAYERS 6
#define MTOK    (BB * LL)      // 8192 tokens per input
#define MT2     (2 * MTOK)     // both inputs batched: 16384 tokens
#define QT      32             // queries per attention block
#define KW      160            // key window per block

// ---------------------------------------------------------------------------
// Static device scratch (both sequences concatenated)
// ---------------------------------------------------------------------------
__device__ float g_h   [MT2 * DD];
__device__ float g_qkv [MT2 * 3 * DD];
__device__ float g_d   [MT2 * DD];
__device__ __nv_bfloat16 g_h_hi [MT2 * DD];
__device__ __nv_bfloat16 g_ao_hi[MT2 * DD];
__device__ __nv_bfloat16 g_f1_hi[MT2 * FFD];

#define WQKV_N (NLAYERS * 3 * DD * DD)
#define WO_N   (NLAYERS * DD * DD)
#define W1_N   (NLAYERS * FFD * DD)
#define W2_N   (NLAYERS * DD * FFD)
__device__ __nv_bfloat16 g_wqkv_hi[WQKV_N];
__device__ __nv_bfloat16 g_wo_hi  [WO_N];
__device__ __nv_bfloat16 g_w1_hi  [W1_N];
__device__ __nv_bfloat16 g_w2_hi  [W2_N];

__device__ float g_pp  [2 * BB * 16 * DD];
__device__ float g_pool[2 * BB * DD];
__device__ float g_e   [2 * BB * DD];

// ---------------------------------------------------------------------------
// PTX helpers (non-'a' instructions only: mma.sync / ldmatrix / cp.async)
// ---------------------------------------------------------------------------
__device__ __forceinline__ uint32_t s2u(const void* p) {
    uint32_t a;
    asm("{ .reg .u64 t; cvta.to.shared.u64 t, %1; cvt.u32.u64 %0, t; }"
        : "=r"(a) : "l"(p));
    return a;
}

__device__ __forceinline__ void ldsm4(uint32_t* r, uint32_t addr) {
    asm volatile("ldmatrix.sync.aligned.m8n8.x4.shared.b16 {%0,%1,%2,%3}, [%4];"
                 : "=r"(r[0]), "=r"(r[1]), "=r"(r[2]), "=r"(r[3]) : "r"(addr));
}

__device__ __forceinline__ void mma16816(float* c, const uint32_t* a,
                                         const uint32_t* b) {
    asm volatile(
        "mma.sync.aligned.m16n8k16.row.col.f32.bf16.bf16.f32 "
        "{%0,%1,%2,%3}, {%4,%5,%6,%7}, {%8,%9}, {%0,%1,%2,%3};"
        : "+f"(c[0]), "+f"(c[1]), "+f"(c[2]), "+f"(c[3])
        : "r"(a[0]), "r"(a[1]), "r"(a[2]), "r"(a[3]), "r"(b[0]), "r"(b[1]));
}

#define CPA16(dst, src) \
    asm volatile("cp.async.cg.shared.global [%0], [%1], 16;" \
                 :: "r"(dst), "l"(src))
#define CPCOMMIT() asm volatile("cp.async.commit_group;" ::: "memory")
#define CPWAIT0()  asm volatile("cp.async.wait_group 0;" ::: "memory")
#define STSZERO(dst) \
    asm volatile("st.shared.v4.b32 [%0], {%1,%1,%1,%1};" \
                 :: "r"(dst), "r"(0u) : "memory")

// ---------------------------------------------------------------------------
// Pure-bf16 mma.sync GEMM:  C[M,N] = Ahi[M,K] @ Bhi[N,K]^T + bias
// CTA tile 128x64, 256 threads (8 warps, 4x2; warp tile 32x32).
// Stage = 64-wide K slice: Ahi 16KB + Bhi 8KB = 24KB; double-buffered =
// 48KB -> 3 CTAs/SM. Per kk: 4 ldsm up front, 8 MMAs back-to-back.
// fp32 register accumulation. SMEM rows 128B, xor swizzle chunk ^= row&7.
// ---------------------------------------------------------------------------
#define OPTA  16384                  // A tile: 128 rows x 128B
#define OPTB  8192                   // B tile:  64 rows x 128B
#define SSTG  (OPTA + OPTB)          // 24KB
#define NSTG  2
#define GSMEM (NSTG * SSTG)          // 48KB

__global__ __launch_bounds__(256, 3) void gemm_mma(
    const __nv_bfloat16* __restrict__ Ahi,
    const __nv_bfloat16* __restrict__ Bhi,
    const float* __restrict__ bias, float* __restrict__ C,
    __nv_bfloat16* __restrict__ Chi,
    int M, int N, int K, int relu)
{
    extern __shared__ char smraw[];
    const uint32_t sb = s2u(smraw);

    const int tid  = threadIdx.x;
    const int wid  = tid >> 5;
    const int lane = tid & 31;
    const int bm   = blockIdx.y * 128;
    const int bn   = blockIdx.x * 64;
    const int wm   = wid >> 1;       // 0..3 (32 rows)
    const int wn   = wid & 1;        // 0..1 (32 cols)

    float acc[2][4][4];
    #pragma unroll
    for (int i = 0; i < 2; i++)
        #pragma unroll
        for (int j = 0; j < 4; j++)
            #pragma unroll
            for (int r = 0; r < 4; r++) acc[i][j][r] = 0.f;

    const int nst = K >> 6;          // 64-wide K slices

    // loader: 6 cp.async/thread: A rows lr0+{0,32,64,96}, B rows lr0+{0,32}
    const int lr0 = tid >> 3;               // 0..31
    const int lc  = tid & 7;                // 16B chunk index 0..7
    const uint32_t swch = (uint32_t)((lc ^ (lr0 & 7)) << 4);  // rows+32k share

    #define LOADSTAGE(S) do {                                               \
        int col = ((S) << 6) + (lc << 3);                                   \
        uint32_t base = sb + ((S) & 1) * SSTG;                              \
        _Pragma("unroll")                                                   \
        for (int i4 = 0; i4 < 4; i4++) {                                    \
            int rr = lr0 + (i4 << 5);                                       \
            uint32_t d = (uint32_t)(rr << 7) + swch;                        \
            CPA16(base + d, Ahi + (size_t)(bm + rr) * K + col);             \
        }                                                                   \
        _Pragma("unroll")                                                   \
        for (int i2 = 0; i2 < 2; i2++) {                                    \
            int rr = lr0 + (i2 << 5);                                       \
            uint32_t d = (uint32_t)(rr << 7) + swch;                        \
            CPA16(base + OPTA + d, Bhi + (size_t)(bn + rr) * K + col);      \
        }                                                                   \
    } while (0)

    // fragment addressing (canonical ldmatrix, swizzled chunks)
    const int lr  = lane & 15;
    const int lh  = lane >> 4;
    const int s7  = lr & 7;
    const uint32_t arow0 = (uint32_t)((wm * 32 +  0 + lr) << 7);
    const uint32_t arow1 = (uint32_t)((wm * 32 + 16 + lr) << 7);
    const uint32_t brow0 = (uint32_t)((wn * 32 +  0 + lr) << 7);
    const uint32_t brow1 = (uint32_t)((wn * 32 + 16 + lr) << 7);

    LOADSTAGE(0); CPCOMMIT();
    CPWAIT0();
    __syncthreads();           // stage 0 visible to all warps

    for (int s = 0; s < nst; s++) {
        if (s + 1 < nst) LOADSTAGE(s + 1);
        CPCOMMIT();            // uniform group accounting

        const uint32_t sS   = sb + (s & 1) * SSTG;
        const uint32_t sAhi = sS;
        const uint32_t sBhi = sS + OPTA;

        #pragma unroll
        for (int kk = 0; kk < 4; kk++) {
            const uint32_t chs = (uint32_t)((((kk << 1) | lh) ^ s7) << 4);
            uint32_t ah[2][4];
            uint32_t bh[2][2], bh2[2][2];
            uint32_t r[4];

            ldsm4(ah[0], sAhi + arow0 + chs);
            ldsm4(ah[1], sAhi + arow1 + chs);
            ldsm4(r, sBhi + brow0 + chs);
            bh[0][0] = r[0]; bh[0][1] = r[2];
            bh[1][0] = r[1]; bh[1][1] = r[3];
            ldsm4(r, sBhi + brow1 + chs);
            bh2[0][0] = r[0]; bh2[0][1] = r[2];
            bh2[1][0] = r[1]; bh2[1][1] = r[3];

            #pragma unroll
            for (int mt = 0; mt < 2; mt++) {
                #pragma unroll
                for (int nt = 0; nt < 2; nt++) {
                    mma16816(acc[mt][nt],     ah[mt], bh[nt]);
                    mma16816(acc[mt][nt + 2], ah[mt], bh2[nt]);
                }
            }
        }

        CPWAIT0();             // stage s+1 loads complete
        __syncthreads();       // stage s+1 visible; all warps done with s
    }

    // Epilogue
    const int group = lane >> 2;
    const int tig   = lane & 3;
    #pragma unroll
    for (int mt = 0; mt < 2; mt++) {
        #pragma unroll
        for (int half = 0; half < 2; half++) {
            const int row = bm + wm * 32 + mt * 16 + group + half * 8;
            #pragma unroll
            for (int nt = 0; nt < 4; nt++) {
                const int col = bn + wn * 32 + nt * 8 + tig * 2;
                float v0 = acc[mt][nt][half * 2 + 0] + bias[col];
                float v1 = acc[mt][nt][half * 2 + 1] + bias[col + 1];
                if (relu) { v0 = fmaxf(v0, 0.f); v1 = fmaxf(v1, 0.f); }
                if (C) {
                    float2 o = make_float2(v0, v1);
                    *(float2*)(C + (size_t)row * N + col) = o;
                }
                if (Chi) {
                    __nv_bfloat162 hp;
                    hp.x = __float2bfloat16(v0);
                    hp.y = __float2bfloat16(v1);
                    *(__nv_bfloat162*)(Chi + (size_t)row * N + col) = hp;
                }
            }
        }
    }
}

// ---------------------------------------------------------------------------
// fp32 -> bf16 (weights), vectorized
// ---------------------------------------------------------------------------
__global__ void conv_kernel(const float* __restrict__ s,
                            __nv_bfloat16* __restrict__ hi, int n)
{
    int i = (blockIdx.x * 256 + threadIdx.x) * 4;
    if (i < n) {
        float4 v = *(const float4*)(s + i);
        __nv_bfloat162 h0, h1;
        h0.x = __float2bfloat16(v.x); h0.y = __float2bfloat16(v.y);
        h1.x = __float2bfloat16(v.z); h1.y = __float2bfloat16(v.w);
        *(__nv_bfloat162*)(hi + i)     = h0;
        *(__nv_bfloat162*)(hi + i + 2) = h1;
    }
}

// init h = concat(x, y), plus bf16 hi (vectorized; MTOK*DD % 4 == 0)
__global__ void hinit_kernel(const float* __restrict__ x,
                             const float* __restrict__ y,
                             float* __restrict__ h,
                             __nv_bfloat16* __restrict__ hi)
{
    int i = (blockIdx.x * 256 + threadIdx.x) * 4;
    if (i < MT2 * DD) {
        float4 v = (i < MTOK * DD) ? *(const float4*)(x + i)
                                   : *(const float4*)(y + i - MTOK * DD);
        *(float4*)(h + i) = v;
        __nv_bfloat162 h0, h1;
        h0.x = __float2bfloat16(v.x); h0.y = __float2bfloat16(v.y);
        h1.x = __float2bfloat16(v.z); h1.y = __float2bfloat16(v.w);
        *(__nv_bfloat162*)(hi + i)     = h0;
        *(__nv_bfloat162*)(hi + i + 2) = h1;
    }
}

// ---------------------------------------------------------------------------
// Banded attention v3 (|q-k| <= 64), fp32 math. Emits bf16 hi only.
//  - Phase 2: Q row held in 64 registers (loaded once) -> zero Q smem re-reads
//  - Phase 4: two q per thread (16 q-groups x 16 dim-parts) -> V smem
//    traffic halved; V reads broadcast across the two q-halves of each warp
//  - single K/V buffer; V overwrites K during softmax; 74KB smem, 2 CTAs/SM
// ---------------------------------------------------------------------------
#define KVSTR 68
#define PSTR  161
#define ATTN_SMEM_FLOATS (32 * KVSTR + 160 * KVSTR + 32 * PSTR + 32 * 8)
#define ATTN_SMEM_BYTES  (ATTN_SMEM_FLOATS * 4)   // 73,856 B

__global__ __launch_bounds__(256) void attn_kernel(
    const float* __restrict__ qkv, __nv_bfloat16* __restrict__ ohi)
{
    extern __shared__ float sm[];
    float (*Qs)[KVSTR] = (float(*)[KVSTR])(sm);
    float (*KV)[KVSTR] = (float(*)[KVSTR])(sm + 32 * KVSTR);
    float (*P)[PSTR]   = (float(*)[PSTR])(sm + (32 + 160) * KVSTR);
    float (*red)[8]    = (float(*)[8])(sm + (32 + 160) * KVSTR + 32 * PSTR);
    const uint32_t sQ  = s2u(Qs);
    const uint32_t sKV = s2u(KV);

    const int qt  = blockIdx.x;
    const int hh  = blockIdx.y;
    const int b   = blockIdx.z;
    const int tid = threadIdx.x;
    const int l0  = qt * QT;
    const int k0  = l0 - 64;

    // Phase 1: cp.async Q + K
    {
        int row = tid >> 4, c = tid & 15;
        #pragma unroll
        for (int r2 = 0; r2 < 2; r2++) {
            int rr = row + r2 * 16;
            CPA16(sQ + (uint32_t)(rr * (KVSTR * 4) + c * 16),
                  qkv + ((size_t)(b * LL + l0 + rr)) * (3 * DD) + hh * 64 + c * 4);
        }
        #pragma unroll
        for (int r10 = 0; r10 < 10; r10++) {
            int rr = row + r10 * 16;
            int kg = k0 + rr;
            uint32_t dst = sKV + (uint32_t)(rr * (KVSTR * 4) + c * 16);
            if (kg >= 0 && kg < LL)
                CPA16(dst, qkv + ((size_t)(b * LL + kg)) * (3 * DD) + DD +
                           hh * 64 + c * 4);
            else
                STSZERO(dst);
        }
    }
    CPCOMMIT(); CPWAIT0();
    __syncthreads();

    // Phase 2: scores; Q row in registers (loaded once)
    const int q    = tid >> 3;
    const int part = tid & 7;
    const int ql   = l0 + q;
    float4 qreg[16];
    {
        const float4* qr = (const float4*)Qs[q];
        #pragma unroll
        for (int d4 = 0; d4 < 16; d4++) qreg[d4] = qr[d4];
    }
    #pragma unroll 1
    for (int j = 0; j < KW / 8; j++) {
        int kk = part + 8 * j;
        int kg = k0 + kk;
        int dl = ql - kg;
        float s = -1e30f;
        if (kg >= 0 && kg < LL && dl >= -64 && dl <= 64) {
            const float4* kr = (const float4*)KV[kk];
            float dot = 0.f;
            #pragma unroll
            for (int d4 = 0; d4 < 16; d4++) {
                float4 a = qreg[d4], kkv = kr[d4];
                dot = fmaf(a.x, kkv.x, dot);
                dot = fmaf(a.y, kkv.y, dot);
                dot = fmaf(a.z, kkv.z, dot);
                dot = fmaf(a.w, kkv.w, dot);
            }
            s = dot * 0.125f;
        }
        P[q][kk] = s;
    }
    __syncthreads();   // scores done; K no longer needed

    // Phase 3a: start V load (overwrites K buffer)
    {
        int row = tid >> 4, c = tid & 15;
        #pragma unroll
        for (int r10 = 0; r10 < 10; r10++) {
            int rr = row + r10 * 16;
            int kg = k0 + rr;
            uint32_t dst = sKV + (uint32_t)(rr * (KVSTR * 4) + c * 16);
            if (kg >= 0 && kg < LL)
                CPA16(dst, qkv + ((size_t)(b * LL + kg)) * (3 * DD) + 2 * DD +
                           hh * 64 + c * 4);
            else
                STSZERO(dst);
        }
    }
    CPCOMMIT();

    // Phase 3b: softmax (overlaps V arrival)
    float m = -1e30f;
    for (int kk = part; kk < KW; kk += 8) m = fmaxf(m, P[q][kk]);
    red[q][part] = m;
    __syncthreads();
    float mq = red[q][0];
    #pragma unroll
    for (int j = 1; j < 8; j++) mq = fmaxf(mq, red[q][j]);
    __syncthreads();
    float ssum = 0.f;
    for (int kk = part; kk < KW; kk += 8) {
        float sc = P[q][kk];
        float e = (sc > -1e29f) ? __expf(sc - mq) : 0.f;
        P[q][kk] = e;
        ssum += e;
    }
    red[q][part] = ssum;
    CPWAIT0();
    __syncthreads();

    // Phase 4: P @ V, two q per thread (halves V smem traffic)
    const int q0  = tid >> 4;          // 0..15 -> q in {q0, q0+16}
    const int p16 = tid & 15;          // dims p16*4 .. p16*4+3
    float tot0 = 0.f, tot1 = 0.f;
    #pragma unroll
    for (int j = 0; j < 8; j++) {
        tot0 += red[q0][j];
        tot1 += red[q0 + 16][j];
    }
    const float rinv0 = 1.f / tot0;
    const float rinv1 = 1.f / tot1;

    float o0[4] = {0, 0, 0, 0};
    float o1[4] = {0, 0, 0, 0};
    #pragma unroll 1
    for (int kk = 0; kk < KW; kk++) {
        float pa = P[q0][kk];
        float pb = P[q0 + 16][kk];
        float4 v = *(const float4*)&KV[kk][p16 * 4];
        o0[0] = fmaf(pa, v.x, o0[0]); o0[1] = fmaf(pa, v.y, o0[1]);
        o0[2] = fmaf(pa, v.z, o0[2]); o0[3] = fmaf(pa, v.w, o0[3]);
        o1[0] = fmaf(pb, v.x, o1[0]); o1[1] = fmaf(pb, v.y, o1[1]);
        o1[2] = fmaf(pb, v.z, o1[2]); o1[3] = fmaf(pb, v.w, o1[3]);
    }
    {
        size_t ob0 = ((size_t)(b * LL + l0 + q0)) * DD + hh * 64 + p16 * 4;
        size_t ob1 = ob0 + (size_t)16 * DD;
        __nv_bfloat162 w0, w1;
        w0.x = __float2bfloat16(o0[0] * rinv0);
        w0.y = __float2bfloat16(o0[1] * rinv0);
        w1.x = __float2bfloat16(o0[2] * rinv0);
        w1.y = __float2bfloat16(o0[3] * rinv0);
        *(__nv_bfloat162*)(ohi + ob0)     = w0;
        *(__nv_bfloat162*)(ohi + ob0 + 2) = w1;
        w0.x = __float2bfloat16(o1[0] * rinv1);
        w0.y = __float2bfloat16(o1[1] * rinv1);
        w1.x = __float2bfloat16(o1[2] * rinv1);
        w1.y = __float2bfloat16(o1[3] * rinv1);
        *(__nv_bfloat162*)(ohi + ob1)     = w0;
        *(__nv_bfloat162*)(ohi + ob1 + 2) = w1;
    }
}

// ---------------------------------------------------------------------------
// Fused residual add + LayerNorm (in place), optional bf16 hi emission.
// ---------------------------------------------------------------------------
__global__ __launch_bounds__(256) void add_ln_kernel(
    float* __restrict__ h, const float* __restrict__ delta,
    const float* __restrict__ gam, const float* __restrict__ bta, int D,
    __nv_bfloat16* __restrict__ ohi)
{
    const int row = blockIdx.x;
    const int tid = threadIdx.x;
    float xv[3];
    float s = 0.f, s2 = 0.f;
    #pragma unroll
    for (int j = 0; j < 3; j++) {
        int i = tid + j * 256;
        if (i < D) {
            float v = h[(size_t)row * D + i];
            if (delta) v += delta[(size_t)row * D + i];
            xv[j] = v;
            s += v;
            s2 += v * v;
        }
    }
    __shared__ float rs[8], rs2[8];
    __shared__ float sh_mean, sh_rstd;
    #pragma unroll
    for (int o = 16; o > 0; o >>= 1) {
        s  += __shfl_xor_sync(0xffffffffu, s, o);
        s2 += __shfl_xor_sync(0xffffffffu, s2, o);
    }
    if ((tid & 31) == 0) { rs[tid >> 5] = s; rs2[tid >> 5] = s2; }
    __syncthreads();
    if (tid == 0) {
        float ts = 0.f, ts2 = 0.f;
        #pragma unroll
        for (int w = 0; w < 8; w++) { ts += rs[w]; ts2 += rs2[w]; }
        float mean = ts / (float)D;
        float var = ts2 / (float)D - mean * mean;
        sh_mean = mean;
        sh_rstd = rsqrtf(var + 1e-5f);
    }
    __syncthreads();
    float mean = sh_mean, rstd = sh_rstd;
    #pragma unroll
    for (int j = 0; j < 3; j++) {
        int i = tid + j * 256;
        if (i < D) {
            float v = (xv[j] - mean) * rstd * gam[i] + bta[i];
            h[(size_t)row * D + i] = v;
            if (ohi)
                ohi[(size_t)row * D + i] = __float2bfloat16(v);
        }
    }
}

// ---------------------------------------------------------------------------
// Pooling, embedding, cosine (2*BB batches)
// ---------------------------------------------------------------------------
__global__ void pool_partial_kernel(const float* __restrict__ h, float* __restrict__ pp)
{
    const int c = blockIdx.x;
    const int b = blockIdx.y;
    for (int d = threadIdx.x; d < DD; d += 256) {
        float a = 0.f;
        int l0 = c * 64;
        for (int l = l0; l < l0 + 64; l++)
            a += h[((size_t)(b * LL + l)) * DD + d];
        pp[(size_t)(b * 16 + c) * DD + d] = a;
    }
}

__global__ void pool_reduce_kernel(const float* __restrict__ pp, float* __restrict__ pool)
{
    const int b = blockIdx.x;
    for (int d = threadIdx.x; d < DD; d += 256) {
        float a = 0.f;
        #pragma unroll
        for (int c = 0; c < 16; c++)
            a += pp[(size_t)(b * 16 + c) * DD + d];
        pool[(size_t)b * DD + d] = a;
    }
}

__global__ __launch_bounds__(256) void embed_kernel(
    const float* __restrict__ e, const float* __restrict__ We,
    const float* __restrict__ be, float* __restrict__ out)
{
    const int b = blockIdx.x;
    __shared__ float es[DD];
    for (int i = threadIdx.x; i < DD; i += 256)
        es[i] = e[(size_t)b * DD + i];
    __syncthreads();
    for (int n = threadIdx.x; n < DD; n += 256) {
        const float4* wr = (const float4*)(We + (size_t)n * DD);
        const float4* er = (const float4*)es;
        float a = 0.f;
        #pragma unroll 4
        for (int d4 = 0; d4 < DD / 4; d4++) {
            float4 w = wr[d4];
            float4 ev = er[d4];
            a = fmaf(w.x, ev.x, a); a = fmaf(w.y, ev.y, a);
            a = fmaf(w.z, ev.z, a); a = fmaf(w.w, ev.w, a);
        }
        a += be[n];
        out[(size_t)b * DD + n] = fmaxf(a, 0.f);
    }
}

__global__ void cos_kernel(const float* __restrict__ e, float* __restrict__ out)
{
    const int w = threadIdx.x >> 5;
    const int lane = threadIdx.x & 31;
    if (w >= BB) return;
    float dot = 0.f, nx2 = 0.f, ny2 = 0.f;
    for (int d = lane; d < DD; d += 32) {
        float a = e[(size_t)w * DD + d];
        float c = e[(size_t)(w + BB) * DD + d];
        dot = fmaf(a, c, dot);
        nx2 = fmaf(a, a, nx2);
        ny2 = fmaf(c, c, ny2);
    }
    #pragma unroll
    for (int o = 16; o > 0; o >>= 1) {
        dot += __shfl_xor_sync(0xffffffffu, dot, o);
        nx2 += __shfl_xor_sync(0xffffffffu, nx2, o);
        ny2 += __shfl_xor_sync(0xffffffffu, ny2, o);
    }
    if (lane == 0) {
        float nx = fmaxf(sqrtf(nx2), 1e-8f);
        float ny = fmaxf(sqrtf(ny2), 1e-8f);
        out[w] = dot / (nx * ny);
    }
}

// ---------------------------------------------------------------------------
// Host orchestration
// ---------------------------------------------------------------------------
static void launch_gemm(const __nv_bfloat16* Ahi, const __nv_bfloat16* Bhi,
                        const float* bias, float* C, __nv_bfloat16* Chi,
                        int M, int N, int K, int relu)
{
    dim3 grid(N / 64, M / 128);
    gemm_mma<<<grid, 256, GSMEM>>>(Ahi, Bhi, bias, C, Chi, M, N, K, relu);
}

extern "C" void kernel_launch(void* const* d_in, const int* in_sizes, int n_in,
                              void* d_out, int out_size)
{
    (void)in_sizes; (void)n_in; (void)out_size;
    const float* x    = (const float*)d_in[0];
    const float* y    = (const float*)d_in[3];
    const float* Wqkv = (const float*)d_in[6];
    const float* bqkv = (const float*)d_in[7];
    const float* Wo   = (const float*)d_in[8];
    const float* bo   = (const float*)d_in[9];
    const float* ln1g = (const float*)d_in[10];
    const float* ln1b = (const float*)d_in[11];
    const float* W1   = (const float*)d_in[12];
    const float* b1   = (const float*)d_in[13];
    const float* W2   = (const float*)d_in[14];
    const float* b2   = (const float*)d_in[15];
    const float* ln2g = (const float*)d_in[16];
    const float* ln2b = (const float*)d_in[17];
    const float* lneg = (const float*)d_in[18];
    const float* lneb = (const float*)d_in[19];
    const float* We   = (const float*)d_in[20];
    const float* be   = (const float*)d_in[21];
    float* out = (float*)d_out;

    float *ph, *pqkv, *pd, *ppp, *ppool, *pe;
    __nv_bfloat16 *phh, *paoh, *pf1h;
    __nv_bfloat16 *pwqh, *pwoh, *pw1h, *pw2h;
    cudaGetSymbolAddress((void**)&ph,    g_h);
    cudaGetSymbolAddress((void**)&pqkv,  g_qkv);
    cudaGetSymbolAddress((void**)&pd,    g_d);
    cudaGetSymbolAddress((void**)&ppp,   g_pp);
    cudaGetSymbolAddress((void**)&ppool, g_pool);
    cudaGetSymbolAddress((void**)&pe,    g_e);
    cudaGetSymbolAddress((void**)&phh,   g_h_hi);
    cudaGetSymbolAddress((void**)&paoh,  g_ao_hi);
    cudaGetSymbolAddress((void**)&pf1h,  g_f1_hi);
    cudaGetSymbolAddress((void**)&pwqh,  g_wqkv_hi);
    cudaGetSymbolAddress((void**)&pwoh,  g_wo_hi);
    cudaGetSymbolAddress((void**)&pw1h,  g_w1_hi);
    cudaGetSymbolAddress((void**)&pw2h,  g_w2_hi);

    cudaFuncSetAttribute(attn_kernel,
                         cudaFuncAttributeMaxDynamicSharedMemorySize,
                         ATTN_SMEM_BYTES);
    cudaFuncSetAttribute(gemm_mma,
                         cudaFuncAttributeMaxDynamicSharedMemorySize, GSMEM);

    // Launch order keeps gemm_mma (QKV, layer 0) early for ncu capture.
    conv_kernel<<<(WQKV_N / 4 + 255) / 256, 256>>>(Wqkv, pwqh, WQKV_N);
    conv_kernel<<<(WO_N   / 4 + 255) / 256, 256>>>(Wo,   pwoh, WO_N);
    hinit_kernel<<<(MT2 * DD / 4 + 255) / 256, 256>>>(x, y, ph, phh);

    for (int l = 0; l < NLAYERS; l++) {
        // QKV projection (fp32 out, consumed by attention)
        launch_gemm(phh,
                    pwqh + (size_t)l * 3 * DD * DD,
                    bqkv + (size_t)l * 3 * DD,
                    pqkv, nullptr, MT2, 3 * DD, DD, 0);
        // Banded attention over 16 batched sequences -> bf16 hi
        attn_kernel<<<dim3(LL / QT, HH, 2 * BB), 256, ATTN_SMEM_BYTES>>>(
            pqkv, paoh);
        // Output projection (fp32 out)
        launch_gemm(paoh,
                    pwoh + (size_t)l * DD * DD,
                    bo + (size_t)l * DD,
                    pd, nullptr, MT2, DD, DD, 0);
        // h = LN(h + attn_proj), emit hi
        add_ln_kernel<<<MT2, 256>>>(ph, pd, ln1g + (size_t)l * DD,
                                    ln1b + (size_t)l * DD, DD, phh);
        // Deferred weight conversion for FF paths (first use is next launch)
        if (l == 0) {
            conv_kernel<<<(W1_N / 4 + 255) / 256, 256>>>(W1, pw1h, W1_N);
            conv_kernel<<<(W2_N / 4 + 255) / 256, 256>>>(W2, pw2h, W2_N);
        }
        // FF1 + ReLU -> bf16 hi only
        launch_gemm(phh,
                    pw1h + (size_t)l * FFD * DD,
                    b1 + (size_t)l * FFD,
                    nullptr, pf1h, MT2, FFD, DD, 1);
        // FF2 (fp32 out)
        launch_gemm(pf1h,
                    pw2h + (size_t)l * DD * FFD,
                    b2 + (size_t)l * DD,
                    pd, nullptr, MT2, DD, FFD, 0);
        // h = LN(h + ff), emit hi
        add_ln_kernel<<<MT2, 256>>>(ph, pd, ln2g + (size_t)l * DD,
                                    ln2b + (size_t)l * DD, DD, phh);
    }

    pool_partial_kernel<<<dim3(16, 2 * BB), 256>>>(ph, ppp);
    pool_reduce_kernel<<<2 * BB, 256>>>(ppp, ppool);
    add_ln_kernel<<<2 * BB, 256>>>(ppool, (const float*)nullptr, lneg, lneb, DD,
                                   nullptr);
    embed_kernel<<<2 * BB, 256>>>(ppool, We, be, pe);

    cos_kernel<<<1, 256>>>(pe, out);
}